// round 15
// baseline (speedup 1.0000x reference)
#include <cuda_runtime.h>
#include <cuda_fp16.h>
#include <math.h>
#include <stdint.h>

#define Bc 32
#define Tc 128
#define Mc 1290
#define Cc 512
#define Hc 8
#define NBLK 4
#define TOPK 8
#define KVS 1024

static __device__ float d_inp[Bc*Tc*Cc];
static __device__ float d_mem[(size_t)Bc*Mc*Cc];
static __device__ float d_qb [(size_t)Bc*Mc*Cc];
static __device__ float d_kvs[(size_t)Bc*Tc*KVS];
static __device__ float d_ao [(size_t)Bc*Mc*Cc];
static __device__ float d_h2 [(size_t)Bc*Mc*Cc];
static __device__ float d_gt [(size_t)Bc*Mc*2*Cc];
static __device__ float d_rm [Bc*Cc];
static __device__ float d_gi [Bc*2*Cc];
static __device__ float d_bkv[2*Cc];
// half activation mirrors
static __device__ __half d_ipts_h[Bc*Tc*Cc];
static __device__ __half d_inp_h [Bc*Tc*Cc];
static __device__ __half d_mem_h [(size_t)Bc*Mc*Cc];
static __device__ __half d_h1_h  [(size_t)Bc*Mc*Cc];
static __device__ __half d_tm_h  [(size_t)Bc*Mc*Cc];
static __device__ __half d_nm_h  [(size_t)Bc*Mc*Cc];
// half weights (K-major)
static __device__ __half d_WqT[Cc*Cc];
static __device__ __half d_WkvT[2*Cc*Cc];
static __device__ __half d_WmT[Cc*Cc];
static __device__ __half d_WpT[Cc*Cc];
static __device__ __half d_WmgT[Cc*2*Cc];

#define F_INF __int_as_float(0x7f800000)

__device__ __forceinline__ uint32_t smem_u32(const void* p){
    uint32_t a;
    asm("{ .reg .u64 t; cvta.to.shared.u64 t, %1; cvt.u32.u64 %0, t; }" : "=r"(a) : "l"(p));
    return a;
}
__device__ __forceinline__ void mma_f16(float* d, const uint32_t* a, const uint32_t* b){
    asm volatile("mma.sync.aligned.m16n8k16.row.col.f32.f16.f16.f32 "
        "{%0,%1,%2,%3}, {%4,%5,%6,%7}, {%8,%9}, {%0,%1,%2,%3};"
        : "+f"(d[0]), "+f"(d[1]), "+f"(d[2]), "+f"(d[3])
        : "r"(a[0]), "r"(a[1]), "r"(a[2]), "r"(a[3]), "r"(b[0]), "r"(b[1]));
}
__device__ __forceinline__ void ldsm4(uint32_t* r, uint32_t addr){
    asm volatile("ldmatrix.sync.aligned.m8n8.x4.shared.b16 {%0,%1,%2,%3}, [%4];"
        : "=r"(r[0]), "=r"(r[1]), "=r"(r[2]), "=r"(r[3]) : "r"(addr));
}
__device__ __forceinline__ void cp16(uint32_t dst, const void* src, int sz){
    asm volatile("cp.async.ca.shared.global [%0], [%1], 16, %2;"
                 :: "r"(dst), "l"(src), "r"(sz) : "memory");
}

// ============ all-half GEMM: 128x128 tile, K-chunk 64, 3-stage cp.async ============
// One barrier per 64-K chunk: 24 LDSM + 64 HMMA between barriers.
#define APH 72
#define CHH (128*APH)                 // halves per A (or B) chunk
#define SSZ (2*CHH)                   // stage size in halves
#define NSTG 3
#define TG_SMEM (NSTG*SSZ*2)          // bytes = 110592
__global__ __launch_bounds__(256) void f16_gemm_kernel(
    const __half* __restrict__ A, const __half* __restrict__ WT,
    const float* __restrict__ bias, float* __restrict__ outf,
    __half* __restrict__ outh,
    int Nrows, int K, int NO, int relu)
{
    extern __shared__ __half smh[];
    int tid = threadIdx.x;
    int wid = tid >> 5, lane = tid & 31;
    int wm = wid & 3, wn = wid >> 2;
    int lr = lane >> 2, lc = lane & 3;
    int row0 = blockIdx.y * 128;
    int col0 = blockIdx.x * 128;

    float acc[2][8][4];
    #pragma unroll
    for (int i=0;i<2;i++)
        #pragma unroll
        for (int j=0;j<8;j++)
            #pragma unroll
            for (int l=0;l<4;l++) acc[i][j][l] = 0.f;

    int arow = tid & 127;
    int seg  = (tid >> 7) * 32;      // 0 or 32 halves within the 64-half row
    bool apred = (row0 + arow) < Nrows;
    const __half* aptr = A  + (size_t)(row0 + arow)*K + seg;
    const __half* bptr = WT + (size_t)(col0 + arow)*K + seg;
    uint32_t sbase = smem_u32(smh);
    uint32_t adst = sbase + (arow*APH + seg)*2;

    int lt = lane >> 3, lrw = lane & 7;
    uint32_t aoff[2], boff[4];
    #pragma unroll
    for (int ma = 0; ma < 2; ma++) {
        int r = wm*32 + ma*16 + lrw + ((lt & 1) << 3);
        int kk = (lt >> 1) * 8;
        aoff[ma] = (uint32_t)((r*APH + kk) * 2);
    }
    #pragma unroll
    for (int g = 0; g < 4; g++) {
        int n = wn*64 + (g*2 + (lt >> 1))*8 + lrw;
        int kk = (lt & 1) * 8;
        boff[g] = (uint32_t)(CHH*2 + (n*APH + kk) * 2);
    }

    const int nc = K / 64;           // 8 chunks
    int asz = apred ? 16 : 0;

    auto issue = [&](int c){
        uint32_t off = (uint32_t)(c % NSTG) * SSZ*2;
        const __half* as = aptr + c*64;
        const __half* bs = bptr + c*64;
        #pragma unroll
        for (int j = 0; j < 4; j++) {
            cp16(adst + off + j*16,         as + j*8, asz);
            cp16(adst + off + CHH*2 + j*16, bs + j*8, 16);
        }
        asm volatile("cp.async.commit_group;" ::: "memory");
    };

    issue(0); issue(1);
    for (int c = 0; c < nc; c++) {
        asm volatile("cp.async.wait_group 1;" ::: "memory");
        __syncthreads();
        if (c + 2 < nc) issue(c + 2);
        else asm volatile("cp.async.commit_group;" ::: "memory");  // keep group count
        uint32_t buf = sbase + (uint32_t)(c % NSTG)*SSZ*2;
        #pragma unroll
        for (int ks = 0; ks < 4; ks++) {
            uint32_t kbb = ks*32;     // 16 halves = 32 bytes per k-step
            uint32_t af[2][4];
            #pragma unroll
            for (int ma = 0; ma < 2; ma++)
                ldsm4(af[ma], buf + aoff[ma] + kbb);
            uint32_t bf[8][2];
            #pragma unroll
            for (int g = 0; g < 4; g++) {
                uint32_t r4[4];
                ldsm4(r4, buf + boff[g] + kbb);
                bf[g*2  ][0] = r4[0]; bf[g*2  ][1] = r4[1];
                bf[g*2+1][0] = r4[2]; bf[g*2+1][1] = r4[3];
            }
            #pragma unroll
            for (int ma = 0; ma < 2; ma++)
                #pragma unroll
                for (int na = 0; na < 8; na++)
                    mma_f16(acc[ma][na], af[ma], bf[na]);
        }
    }

    #pragma unroll
    for (int ma = 0; ma < 2; ma++) {
        int r1 = row0 + wm*32 + ma*16 + lr;
        int r2 = r1 + 8;
        #pragma unroll
        for (int na = 0; na < 8; na++) {
            int col = col0 + wn*64 + na*8 + lc*2;
            float bx = bias[col], by = bias[col+1];
            float2 o1 = make_float2(acc[ma][na][0] + bx, acc[ma][na][1] + by);
            float2 o2 = make_float2(acc[ma][na][2] + bx, acc[ma][na][3] + by);
            if (relu) {
                o1.x = fmaxf(o1.x,0.f); o1.y = fmaxf(o1.y,0.f);
                o2.x = fmaxf(o2.x,0.f); o2.y = fmaxf(o2.y,0.f);
            }
            if (outf) {
                if (r1 < Nrows) *reinterpret_cast<float2*>(outf + (size_t)r1*NO + col) = o1;
                if (r2 < Nrows) *reinterpret_cast<float2*>(outf + (size_t)r2*NO + col) = o2;
            }
            if (outh) {
                if (r1 < Nrows)
                    *reinterpret_cast<__half2*>(outh + (size_t)r1*NO + col) = __floats2half2_rn(o1.x, o1.y);
                if (r2 < Nrows)
                    *reinterpret_cast<__half2*>(outh + (size_t)r2*NO + col) = __floats2half2_rn(o2.x, o2.y);
            }
        }
    }
}

// ============ preamble convert ============
__global__ void convert_pre_kernel(const float* __restrict__ ipts, const float* __restrict__ memory,
                                   __half* __restrict__ ipts_h, __half* __restrict__ mem_h,
                                   __half* __restrict__ tm_h)
{
    size_t i = (size_t)blockIdx.x*blockDim.x + threadIdx.x;
    size_t st = (size_t)gridDim.x*blockDim.x;
    const size_t ni = (size_t)Bc*Tc*Cc;
    const size_t nm = (size_t)Bc*Mc*Cc;
    for (size_t j = i; j < ni; j += st) ipts_h[j] = __float2half(ipts[j]);
    for (size_t j = i; j < nm; j += st) {
        float v = memory[j];
        mem_h[j] = __float2half(v);
        tm_h[j]  = __float2half(tanhf(v));
    }
}

// ============ batched transpose + half convert + bias concat ============
struct TPack {
    const float* in[6];
    __half* out[6];
    int C[6];
    const float* bk; const float* bv; float* bkv;
};
__global__ __launch_bounds__(256) void transpose_all_kernel(TPack p)
{
    __shared__ float t[32][33];
    int w = blockIdx.z;
    int C = p.C[w];
    int c0 = blockIdx.x*32;
    if (c0 >= C) return;
    int r0 = blockIdx.y*32;
    if (w == 0 && c0 == 0 && r0 == 0) {
        int i = threadIdx.x;
        p.bkv[i*2] = p.bk[i*2]; p.bkv[i*2+1] = p.bk[i*2+1];
        p.bkv[Cc + i*2] = p.bv[i*2]; p.bkv[Cc + i*2+1] = p.bv[i*2+1];
    }
    const float* in = p.in[w];
    __half* out = p.out[w];
    int x = threadIdx.x & 31, y = threadIdx.x >> 5;
    #pragma unroll
    for (int i = 0; i < 4; i++)
        t[y + i*8][x] = in[(size_t)(r0 + y + i*8)*C + c0 + x];
    __syncthreads();
    #pragma unroll
    for (int i = 0; i < 4; i++)
        out[(size_t)(c0 + y + i*8)*Cc + r0 + x] = __float2half(t[x][y + i*8]);
}

// ============ SIMT GEMM (tiny) ============
__global__ __launch_bounds__(256) void gemm_kernel(
    const float* __restrict__ A, const float* __restrict__ W,
    const float* __restrict__ bias, float* __restrict__ out,
    int N, int K, int NO, int relu)
{
    __shared__ float As[16][64];
    __shared__ float Bs[16][64];
    int t  = threadIdx.x;
    int tx = t & 15, ty = t >> 4;
    int row0 = blockIdx.y * 64;
    int col0 = blockIdx.x * 64;
    float acc[4][4] = {};
    for (int k0 = 0; k0 < K; k0 += 16) {
        {
            int r = t >> 2;
            int c4 = (t & 3) * 4;
            float4 av = make_float4(0.f,0.f,0.f,0.f);
            if (row0 + r < N)
                av = *reinterpret_cast<const float4*>(A + (size_t)(row0 + r) * K + k0 + c4);
            As[c4+0][r] = av.x; As[c4+1][r] = av.y; As[c4+2][r] = av.z; As[c4+3][r] = av.w;
        }
        {
            int r  = t >> 4;
            int c4 = (t & 15) * 4;
            float4 bv = *reinterpret_cast<const float4*>(W + (size_t)(k0 + r) * NO + col0 + c4);
            *reinterpret_cast<float4*>(&Bs[r][c4]) = bv;
        }
        __syncthreads();
        #pragma unroll
        for (int kk = 0; kk < 16; kk++) {
            float4 a4 = *reinterpret_cast<const float4*>(&As[kk][ty*4]);
            float4 b4 = *reinterpret_cast<const float4*>(&Bs[kk][tx*4]);
            float a[4] = {a4.x,a4.y,a4.z,a4.w};
            float b[4] = {b4.x,b4.y,b4.z,b4.w};
            #pragma unroll
            for (int i=0;i<4;i++)
                #pragma unroll
                for (int j=0;j<4;j++) acc[i][j] += a[i]*b[j];
        }
        __syncthreads();
    }
    float4 bb = *reinterpret_cast<const float4*>(bias + col0 + tx*4);
    #pragma unroll
    for (int i=0;i<4;i++) {
        int r = row0 + ty*4 + i;
        if (r >= N) continue;
        float4 o4;
        o4.x = acc[i][0] + bb.x; o4.y = acc[i][1] + bb.y;
        o4.z = acc[i][2] + bb.z; o4.w = acc[i][3] + bb.w;
        if (relu) {
            o4.x = fmaxf(o4.x,0.f); o4.y = fmaxf(o4.y,0.f);
            o4.z = fmaxf(o4.z,0.f); o4.w = fmaxf(o4.w,0.f);
        }
        *reinterpret_cast<float4*>(out + (size_t)r * NO + col0 + tx*4) = o4;
    }
}

// ============ warp reductions (x4-interleaved) ============
__device__ __forceinline__ void warpMax4(float* c){
    #pragma unroll
    for (int o=16;o;o>>=1){
        #pragma unroll
        for (int qq=0;qq<4;qq++) c[qq] = fmaxf(c[qq], __shfl_xor_sync(0xffffffffu, c[qq], o));
    }
}
__device__ __forceinline__ void warpSum4(float* c){
    #pragma unroll
    for (int o=16;o;o>>=1){
        #pragma unroll
        for (int qq=0;qq<4;qq++) c[qq] += __shfl_xor_sync(0xffffffffu, c[qq], o);
    }
}

// ============ top-k attention ============
#define Q_BLOCKS 6
#define SMEM_TOPK ((64*128 + 128*64 + 8*4*64)*4)
__global__ __launch_bounds__(256) void attn_topk_kernel(
    const float* __restrict__ q, const float* __restrict__ kv,
    float* __restrict__ o)
{
    extern __shared__ float sm[];
    float* Kt = sm;
    float* Vs = Kt + 64*128;
    float* sq = Vs + 128*64;

    int tid = threadIdx.x;
    int warp = tid >> 5, lane = tid & 31;
    int bh = blockIdx.x, b = bh / Hc, h = bh % Hc;

    for (int idx = tid; idx < 128*16; idx += 256) {
        int t = idx >> 4, j = idx & 15;
        size_t row = ((size_t)b*Tc + t)*KVS + h*64 + j*4;
        float4 kvv = *reinterpret_cast<const float4*>(kv + row);
        float4 vv  = *reinterpret_cast<const float4*>(kv + row + Cc);
        Kt[(j*4+0)*128 + t] = kvv.x;
        Kt[(j*4+1)*128 + t] = kvv.y;
        Kt[(j*4+2)*128 + t] = kvv.z;
        Kt[(j*4+3)*128 + t] = kvv.w;
        *reinterpret_cast<float4*>(&Vs[t*64 + j*4]) = vv;
    }
    __syncthreads();

    const int nq = (Mc + Q_BLOCKS - 1) / Q_BLOCKS;
    int q0 = blockIdx.y * nq;
    int qend = min(q0 + nq, Mc);
    float* sqw = sq + warp*256;

    for (int qi0 = q0 + warp*4; qi0 < qend; qi0 += 32) {
        #pragma unroll
        for (int f = 0; f < 2; f++) {
            int ff = lane + f*32;
            int qq = ff >> 4, j = ff & 15;
            int qi = qi0 + qq;
            if (qi < qend) {
                float4 qv = *reinterpret_cast<const float4*>(q + ((size_t)b*Mc + qi)*Cc + h*64 + j*4);
                *reinterpret_cast<float4*>(&sqw[qq*64 + j*4]) = qv;
            }
        }
        __syncwarp();
        float s[4][4];
        #pragma unroll
        for (int qq=0;qq<4;qq++)
            #pragma unroll
            for (int j=0;j<4;j++) s[qq][j] = 0.f;
        #pragma unroll 4
        for (int d0 = 0; d0 < 64; d0 += 4) {
            float4 kk4[4];
            #pragma unroll
            for (int dd = 0; dd < 4; dd++)
                kk4[dd] = *reinterpret_cast<const float4*>(&Kt[(d0+dd)*128 + lane*4]);
            #pragma unroll
            for (int qq = 0; qq < 4; qq++) {
                float4 qd = *reinterpret_cast<const float4*>(&sqw[qq*64 + d0]);
                s[qq][0] += qd.x*kk4[0].x + qd.y*kk4[1].x + qd.z*kk4[2].x + qd.w*kk4[3].x;
                s[qq][1] += qd.x*kk4[0].y + qd.y*kk4[1].y + qd.z*kk4[2].y + qd.w*kk4[3].y;
                s[qq][2] += qd.x*kk4[0].z + qd.y*kk4[1].z + qd.z*kk4[2].z + qd.w*kk4[3].z;
                s[qq][3] += qd.x*kk4[0].w + qd.y*kk4[1].w + qd.z*kk4[2].w + qd.w*kk4[3].w;
            }
        }
        #pragma unroll
        for (int qq=0;qq<4;qq++)
            #pragma unroll
            for (int j=0;j<4;j++) s[qq][j] *= 0.125f;

        float thr[4], gmax[4], c[4];
        #pragma unroll
        for (int qq=0;qq<4;qq++)
            c[qq] = fmaxf(fmaxf(s[qq][0],s[qq][1]), fmaxf(s[qq][2],s[qq][3]));
        warpMax4(c);
        #pragma unroll
        for (int qq=0;qq<4;qq++){ gmax[qq] = c[qq]; thr[qq] = c[qq]; }
        #pragma unroll
        for (int it = 1; it < TOPK; it++) {
            #pragma unroll
            for (int qq=0;qq<4;qq++){
                float m = -F_INF;
                #pragma unroll
                for (int j=0;j<4;j++) m = fmaxf(m, (s[qq][j] < thr[qq]) ? s[qq][j] : -F_INF);
                c[qq] = m;
            }
            warpMax4(c);
            #pragma unroll
            for (int qq=0;qq<4;qq++) thr[qq] = c[qq];
        }
        float e[4][4], le[4];
        #pragma unroll
        for (int qq=0;qq<4;qq++){
            le[qq] = 0.f;
            #pragma unroll
            for (int j=0;j<4;j++){ e[qq][j] = __expf(s[qq][j] - gmax[qq]); le[qq] += e[qq][j]; }
        }
        warpSum4(le);

        int d0v = lane*2;
        #pragma unroll
        for (int qq = 0; qq < 4; qq++) {
            int qi = qi0 + qq;
            if (qi >= qend) break;
            float inv = 1.f / le[qq];
            float p[4];
            #pragma unroll
            for (int j=0;j<4;j++) p[j] = (s[qq][j] >= thr[qq]) ? e[qq][j]*inv : 0.f;
            float2 acc = make_float2(0.f, 0.f);
            #pragma unroll
            for (int j=0;j<4;j++) {
                unsigned msk = __ballot_sync(0xffffffffu, p[j] != 0.f);
                while (msk) {
                    int src = __ffs(msk) - 1;
                    msk &= msk - 1;
                    float pv = __shfl_sync(0xffffffffu, p[j], src);
                    int key = src*4 + j;
                    float2 vv = *reinterpret_cast<const float2*>(&Vs[key*64 + d0v]);
                    acc.x += pv*vv.x; acc.y += pv*vv.y;
                }
            }
            *reinterpret_cast<float2*>(o + ((size_t)b*Mc + qi)*Cc + h*64 + d0v) = acc;
        }
    }
}

// ============ hx attention ============
#define SMEM_HX ((64*128 + 128*64 + 32*64 + 8*4*128)*4)
__global__ __launch_bounds__(256) void attn_hx_kernel(
    const float* __restrict__ q, const float* __restrict__ kv,
    float* __restrict__ o)
{
    extern __shared__ float sm[];
    float* Kt = sm;
    float* Vs = Kt + 64*128;
    float* sq = Vs + 128*64;
    float* ps = sq + 32*64;

    int tid = threadIdx.x;
    int warp = tid >> 5, lane = tid & 31;
    int bh = blockIdx.x, b = bh / Hc, h = bh % Hc;
    int q0 = blockIdx.y * 32;

    for (int idx = tid; idx < 32*16; idx += 256) {
        int qi = idx >> 4, j = idx & 15;
        float4 qv = *reinterpret_cast<const float4*>(q + ((size_t)b*Tc + q0 + qi)*Cc + h*64 + j*4);
        *reinterpret_cast<float4*>(&sq[qi*64 + j*4]) = qv;
    }

    float m[4], den[4];
    float2 acc[4];
    #pragma unroll
    for (int i=0;i<4;i++){ m[i] = -F_INF; den[i] = 0.f; acc[i] = make_float2(0.f,0.f); }
    int d0v = lane*2;
    float* psw = ps + warp*512;

    for (int c0 = 0; c0 < Mc; c0 += 128) {
        int nk = min(128, Mc - c0);
        __syncthreads();
        for (int idx = tid; idx < 128*16; idx += 256) {
            int t = idx >> 4, j = idx & 15;
            float4 kvv = make_float4(0.f,0.f,0.f,0.f), vv = kvv;
            if (t < nk) {
                size_t row = ((size_t)b*Mc + c0 + t)*KVS + h*64 + j*4;
                kvv = *reinterpret_cast<const float4*>(kv + row);
                vv  = *reinterpret_cast<const float4*>(kv + row + Cc);
            }
            Kt[(j*4+0)*128 + t] = kvv.x;
            Kt[(j*4+1)*128 + t] = kvv.y;
            Kt[(j*4+2)*128 + t] = kvv.z;
            Kt[(j*4+3)*128 + t] = kvv.w;
            *reinterpret_cast<float4*>(&Vs[t*64 + j*4]) = vv;
        }
        __syncthreads();

        float s[4][4];
        #pragma unroll
        for (int i=0;i<4;i++)
            #pragma unroll
            for (int j=0;j<4;j++) s[i][j] = 0.f;
        #pragma unroll 4
        for (int d0 = 0; d0 < 64; d0 += 4) {
            float4 kk4[4];
            #pragma unroll
            for (int dd = 0; dd < 4; dd++)
                kk4[dd] = *reinterpret_cast<const float4*>(&Kt[(d0+dd)*128 + lane*4]);
            #pragma unroll
            for (int i = 0; i < 4; i++) {
                float4 qd = *reinterpret_cast<const float4*>(&sq[(warp*4+i)*64 + d0]);
                s[i][0] += qd.x*kk4[0].x + qd.y*kk4[1].x + qd.z*kk4[2].x + qd.w*kk4[3].x;
                s[i][1] += qd.x*kk4[0].y + qd.y*kk4[1].y + qd.z*kk4[2].y + qd.w*kk4[3].y;
                s[i][2] += qd.x*kk4[0].z + qd.y*kk4[1].z + qd.z*kk4[2].z + qd.w*kk4[3].z;
                s[i][3] += qd.x*kk4[0].w + qd.y*kk4[1].w + qd.z*kk4[2].w + qd.w*kk4[3].w;
            }
        }
        float lm[4];
        #pragma unroll
        for (int i = 0; i < 4; i++) {
            float mm = -F_INF;
            #pragma unroll
            for (int j=0;j<4;j++) {
                s[i][j] = (lane*4 + j < nk) ? s[i][j]*0.125f : -F_INF;
                mm = fmaxf(mm, s[i][j]);
            }
            lm[i] = mm;
        }
        warpMax4(lm);
        float f[4], le[4];
        #pragma unroll
        for (int i = 0; i < 4; i++) {
            float newm = fmaxf(m[i], lm[i]);
            f[i] = __expf(m[i] - newm);
            m[i] = newm;
            float e0 = __expf(s[i][0]-newm), e1 = __expf(s[i][1]-newm);
            float e2 = __expf(s[i][2]-newm), e3 = __expf(s[i][3]-newm);
            le[i] = e0+e1+e2+e3;
            *reinterpret_cast<float4*>(&psw[i*128 + lane*4]) = make_float4(e0,e1,e2,e3);
        }
        warpSum4(le);
        #pragma unroll
        for (int i = 0; i < 4; i++) {
            den[i] = den[i]*f[i] + le[i];
            acc[i].x *= f[i]; acc[i].y *= f[i];
        }
        __syncwarp();
        #pragma unroll 4
        for (int kk = 0; kk < 128; kk++) {
            float2 vv = *reinterpret_cast<const float2*>(&Vs[kk*64 + d0v]);
            float p0 = psw[0*128 + kk], p1 = psw[1*128 + kk];
            float p2 = psw[2*128 + kk], p3 = psw[3*128 + kk];
            acc[0].x += p0*vv.x; acc[0].y += p0*vv.y;
            acc[1].x += p1*vv.x; acc[1].y += p1*vv.y;
            acc[2].x += p2*vv.x; acc[2].y += p2*vv.y;
            acc[3].x += p3*vv.x; acc[3].y += p3*vv.y;
        }
    }
    #pragma unroll
    for (int i=0;i<4;i++) {
        int qi = q0 + warp*4 + i;
        float invd = 1.f / den[i];
        float2 ov = make_float2(acc[i].x*invd, acc[i].y*invd);
        *reinterpret_cast<float2*>(o + ((size_t)b*Tc + qi)*Cc + h*64 + d0v) = ov;
    }
}

// ============ add + layernorm (float + half outputs) ============
__global__ __launch_bounds__(256) void add_ln_kernel(
    const float* __restrict__ x, const float* __restrict__ r,
    const float* __restrict__ g, const float* __restrict__ bb,
    float* __restrict__ out, __half* __restrict__ outh, int nrows)
{
    int warp = (blockIdx.x * blockDim.x + threadIdx.x) >> 5;
    int lane = threadIdx.x & 31;
    if (warp >= nrows) return;
    const float* xr = x + (size_t)warp * Cc;
    const float* rr = r + (size_t)warp * Cc;
    float vals[16];
    float s = 0.f;
    #pragma unroll
    for (int i=0;i<16;i++) { float vv = xr[lane + i*32] + rr[lane + i*32]; vals[i] = vv; s += vv; }
    #pragma unroll
    for (int o2=16;o2;o2>>=1) s += __shfl_xor_sync(0xffffffffu, s, o2);
    float mu = s * (1.f/512.f);
    float vs = 0.f;
    #pragma unroll
    for (int i=0;i<16;i++){ float d = vals[i]-mu; vs += d*d; }
    #pragma unroll
    for (int o2=16;o2;o2>>=1) vs += __shfl_xor_sync(0xffffffffu, vs, o2);
    float rstd = rsqrtf(vs*(1.f/512.f) + 1e-5f);
    float* outr = out + (size_t)warp * Cc;
    __half* outhr = outh + (size_t)warp * Cc;
    #pragma unroll
    for (int i=0;i<16;i++){
        int cc = lane + i*32;
        float ov = (vals[i]-mu)*rstd*g[cc] + bb[cc];
        outr[cc] = ov;
        outhr[cc] = __float2half(ov);
    }
}

// ============ misc elementwise ============
__global__ void repmean_kernel(const float* __restrict__ inp, const float* __restrict__ rep_w,
                               float* __restrict__ out)
{
    int b = blockIdx.x, c = threadIdx.x;
    const float* base = inp + (size_t)b*Tc*Cc + c;
    float rw = rep_w[c];
    float s = 0.f;
    for (int t=0;t<Tc;t++) s += fmaxf(rw * base[(size_t)t*Cc], 0.f);
    out[b*Cc + c] = s * (1.f/Tc);
}

__global__ void gate_kernel(const float* __restrict__ gates, const float* __restrict__ gi,
                            const float* __restrict__ mem_final, const float* __restrict__ mem0,
                            const float* __restrict__ ib, const float* __restrict__ fb,
                            float* __restrict__ nm, __half* __restrict__ nmh)
{
    size_t n = (size_t)Bc*Mc*Cc;
    size_t i = (size_t)blockIdx.x*blockDim.x + threadIdx.x;
    size_t st = (size_t)gridDim.x*blockDim.x;
    float ibv = ib[0], fbv = fb[0];
    for (; i < n; i += st) {
        int c = (int)(i % Cc);
        size_t bm = i / Cc;
        int b = (int)(bm / Mc);
        float gI = gates[bm*2*Cc + c]      + gi[b*2*Cc + c]      + ibv;
        float gF = gates[bm*2*Cc + Cc + c] + gi[b*2*Cc + Cc + c] + fbv;
        float igv = 1.f/(1.f + __expf(-gI));
        float fgv = 1.f/(1.f + __expf(-gF));
        float ov = igv * tanhf(mem_final[i]) + fgv * mem0[i];
        nm[i] = ov;
        nmh[i] = __float2half(ov);
    }
}

// ============ launch ============
extern "C" void kernel_launch(void* const* d_in, const int* in_sizes, int n_in,
                              void* d_out, int out_size)
{
    const float* ipts   = (const float*)d_in[0];
    const float* memory = (const float*)d_in[1];
    const float* Wq=(const float*)d_in[2],  *bq=(const float*)d_in[3];
    const float* Wk=(const float*)d_in[4],  *bk=(const float*)d_in[5];
    const float* Wv=(const float*)d_in[6],  *bv=(const float*)d_in[7];
    const float* Wm=(const float*)d_in[8],  *bm=(const float*)d_in[9];
    const float* g1=(const float*)d_in[10], *b1=(const float*)d_in[11];
    const float* g2=(const float*)d_in[12], *b2=(const float*)d_in[13];
    const float* Wp=(const float*)d_in[14], *bp=(const float*)d_in[15];
    const float* rep_w=(const float*)d_in[16];
    const float* Wig=(const float*)d_in[17], *big=(const float*)d_in[18];
    const float* Wmg=(const float*)d_in[19], *bmg=(const float*)d_in[20];
    const float* fb=(const float*)d_in[21], *ib=(const float*)d_in[22];

    float* out_nm = (float*)d_out;
    float* out_hx = out_nm + (size_t)Bc*Mc*Cc;

    float *inp,*mem,*qb,*kvs,*ao,*h2,*gt,*rm,*gi,*bkv;
    __half *ipts_h,*inp_h,*mem_h,*h1_h,*tm_h,*nm_h;
    __half *WqT,*WkvT,*WmT,*WpT,*WmgT;
    cudaGetSymbolAddress((void**)&inp, d_inp);
    cudaGetSymbolAddress((void**)&mem, d_mem);
    cudaGetSymbolAddress((void**)&qb,  d_qb);
    cudaGetSymbolAddress((void**)&kvs, d_kvs);
    cudaGetSymbolAddress((void**)&ao,  d_ao);
    cudaGetSymbolAddress((void**)&h2,  d_h2);
    cudaGetSymbolAddress((void**)&gt,  d_gt);
    cudaGetSymbolAddress((void**)&rm,  d_rm);
    cudaGetSymbolAddress((void**)&gi,  d_gi);
    cudaGetSymbolAddress((void**)&bkv, d_bkv);
    cudaGetSymbolAddress((void**)&ipts_h, d_ipts_h);
    cudaGetSymbolAddress((void**)&inp_h,  d_inp_h);
    cudaGetSymbolAddress((void**)&mem_h,  d_mem_h);
    cudaGetSymbolAddress((void**)&h1_h,   d_h1_h);
    cudaGetSymbolAddress((void**)&tm_h,   d_tm_h);
    cudaGetSymbolAddress((void**)&nm_h,   d_nm_h);
    cudaGetSymbolAddress((void**)&WqT, d_WqT);
    cudaGetSymbolAddress((void**)&WkvT, d_WkvT);
    cudaGetSymbolAddress((void**)&WmT, d_WmT);
    cudaGetSymbolAddress((void**)&WpT, d_WpT);
    cudaGetSymbolAddress((void**)&WmgT, d_WmgT);

    cudaFuncSetAttribute(attn_topk_kernel, cudaFuncAttributeMaxDynamicSharedMemorySize, SMEM_TOPK);
    cudaFuncSetAttribute(attn_hx_kernel,   cudaFuncAttributeMaxDynamicSharedMemorySize, SMEM_HX);
    cudaFuncSetAttribute(f16_gemm_kernel,  cudaFuncAttributeMaxDynamicSharedMemorySize, TG_SMEM);

    TPack tp;
    tp.in[0]=Wq;  tp.out[0]=WqT;           tp.C[0]=Cc;
    tp.in[1]=Wk;  tp.out[1]=WkvT;          tp.C[1]=Cc;
    tp.in[2]=Wv;  tp.out[2]=WkvT + Cc*Cc;  tp.C[2]=Cc;
    tp.in[3]=Wm;  tp.out[3]=WmT;           tp.C[3]=Cc;
    tp.in[4]=Wp;  tp.out[4]=WpT;           tp.C[4]=Cc;
    tp.in[5]=Wmg; tp.out[5]=WmgT;          tp.C[5]=2*Cc;
    tp.bk = bk; tp.bv = bv; tp.bkv = bkv;
    transpose_all_kernel<<<dim3(32,16,6), 256>>>(tp);
    convert_pre_kernel<<<2048, 256>>>(ipts, memory, ipts_h, mem_h, tm_h);

    auto tgemm = [&](const __half* A, const __half* WT, const float* bias,
                     float* of, __half* oh, int N, int NO, int relu){
        f16_gemm_kernel<<<dim3(NO/128, (N+127)/128), 256, TG_SMEM>>>(
            A, WT, bias, of, oh, N, Cc, NO, relu);
    };

    // inp = ipts @ Wp + bp (float + half); fused k|v from inp_h
    tgemm(ipts_h, WpT, bp, inp, inp_h, Bc*Tc, Cc, 0);
    tgemm(inp_h, WkvT, bkv, kvs, nullptr, Bc*Tc, KVS, 0);

    for (int blk = 0; blk < NBLK; blk++) {
        tgemm(mem_h, WqT, bq, qb, nullptr, Bc*Mc, Cc, 0);
        attn_topk_kernel<<<dim3(Bc*Hc, Q_BLOCKS), 256, SMEM_TOPK>>>(qb, kvs, ao);
        const float* xres = (blk == 0) ? memory : mem;
        add_ln_kernel<<<(Bc*Mc + 7)/8, 256>>>(xres, ao, g1, b1, mem, mem_h, Bc*Mc);
        tgemm(mem_h, WmT, bm, nullptr, h1_h, Bc*Mc, Cc, 1);
        tgemm(h1_h,  WmT, bm, h2, nullptr, Bc*Mc, Cc, 1);
        add_ln_kernel<<<(Bc*Mc + 7)/8, 256>>>(mem, h2, g2, b2, mem, mem_h, Bc*Mc);
    }

    // gates
    repmean_kernel<<<Bc, Cc>>>(inp, rep_w, rm);
    gemm_kernel<<<dim3(2*Cc/64, 1), 256>>>(rm, Wig, big, gi, Bc, Cc, 2*Cc, 0);
    tgemm(tm_h, WmgT, bmg, gt, nullptr, Bc*Mc, 2*Cc, 0);
    gate_kernel<<<2048, 256>>>(gt, gi, mem, memory, ib, fb, out_nm, nm_h);

    // hx
    tgemm(inp_h, WqT, bq, qb, nullptr, Bc*Tc, Cc, 0);
    tgemm(nm_h, WkvT, bkv, gt, nullptr, Bc*Mc, KVS, 0);
    attn_hx_kernel<<<dim3(Bc*Hc, Tc/32), 256, SMEM_HX>>>(qb, gt, out_hx);
}

// round 16
// speedup vs baseline: 1.0603x; 1.0603x over previous
#include <cuda_runtime.h>
#include <cuda_fp16.h>
#include <math.h>
#include <stdint.h>

#define Bc 32
#define Tc 128
#define Mc 1290
#define Cc 512
#define Hc 8
#define NBLK 4
#define TOPK 8
#define KVS 1024

static __device__ float d_inp[Bc*Tc*Cc];
static __device__ float d_mem[(size_t)Bc*Mc*Cc];
static __device__ float d_qb [(size_t)Bc*Mc*Cc];
static __device__ float d_kvs[(size_t)Bc*Tc*KVS];
static __device__ float d_ao [(size_t)Bc*Mc*Cc];
static __device__ float d_h2 [(size_t)Bc*Mc*Cc];
static __device__ float d_gt [(size_t)Bc*Mc*2*Cc];
static __device__ float d_rm [Bc*Cc];
static __device__ float d_gi [Bc*2*Cc];
static __device__ float d_bkv[2*Cc];
// half activation mirrors
static __device__ __half d_ipts_h[Bc*Tc*Cc];
static __device__ __half d_inp_h [Bc*Tc*Cc];
static __device__ __half d_mem_h [(size_t)Bc*Mc*Cc];
static __device__ __half d_h1_h  [(size_t)Bc*Mc*Cc];
static __device__ __half d_tm_h  [(size_t)Bc*Mc*Cc];
static __device__ __half d_nm_h  [(size_t)Bc*Mc*Cc];
// half weights (K-major)
static __device__ __half d_WqT[Cc*Cc];
static __device__ __half d_WkvT[2*Cc*Cc];
static __device__ __half d_WmT[Cc*Cc];
static __device__ __half d_WpT[Cc*Cc];
static __device__ __half d_WmgT[Cc*2*Cc];

#define F_INF __int_as_float(0x7f800000)

__device__ __forceinline__ uint32_t smem_u32(const void* p){
    uint32_t a;
    asm("{ .reg .u64 t; cvta.to.shared.u64 t, %1; cvt.u32.u64 %0, t; }" : "=r"(a) : "l"(p));
    return a;
}
__device__ __forceinline__ void mma_f16(float* d, const uint32_t* a, const uint32_t* b){
    asm volatile("mma.sync.aligned.m16n8k16.row.col.f32.f16.f16.f32 "
        "{%0,%1,%2,%3}, {%4,%5,%6,%7}, {%8,%9}, {%0,%1,%2,%3};"
        : "+f"(d[0]), "+f"(d[1]), "+f"(d[2]), "+f"(d[3])
        : "r"(a[0]), "r"(a[1]), "r"(a[2]), "r"(a[3]), "r"(b[0]), "r"(b[1]));
}
__device__ __forceinline__ void ldsm4(uint32_t* r, uint32_t addr){
    asm volatile("ldmatrix.sync.aligned.m8n8.x4.shared.b16 {%0,%1,%2,%3}, [%4];"
        : "=r"(r[0]), "=r"(r[1]), "=r"(r[2]), "=r"(r[3]) : "r"(addr));
}
__device__ __forceinline__ void cp16(uint32_t dst, const void* src, int sz){
    asm volatile("cp.async.ca.shared.global [%0], [%1], 16, %2;"
                 :: "r"(dst), "l"(src), "r"(sz) : "memory");
}

// ============ all-half GEMM: 128x128 tile, K-chunk 32, 5-stage cp.async ============
// Tail iterations commit EMPTY groups so wait_group 3 always drains group c.
#define APH 40
#define CHH (128*APH)
#define NSTG 5
#define TG_SMEM (NSTG*2*CHH*2)
__global__ __launch_bounds__(256) void f16_gemm_kernel(
    const __half* __restrict__ A, const __half* __restrict__ WT,
    const float* __restrict__ bias, float* __restrict__ outf,
    __half* __restrict__ outh,
    int Nrows, int K, int NO, int relu)
{
    extern __shared__ __half smh[];
    int tid = threadIdx.x;
    int wid = tid >> 5, lane = tid & 31;
    int wm = wid & 3, wn = wid >> 2;
    int lr = lane >> 2, lc = lane & 3;
    int row0 = blockIdx.y * 128;
    int col0 = blockIdx.x * 128;

    float acc[2][8][4];
    #pragma unroll
    for (int i=0;i<2;i++)
        #pragma unroll
        for (int j=0;j<8;j++)
            #pragma unroll
            for (int l=0;l<4;l++) acc[i][j][l] = 0.f;

    int arow = tid & 127;
    int seg  = (tid >> 7) * 16;
    bool apred = (row0 + arow) < Nrows;
    const __half* aptr = A  + (size_t)(row0 + arow)*K + seg;
    const __half* bptr = WT + (size_t)(col0 + arow)*K + seg;
    uint32_t sbase = smem_u32(smh);
    uint32_t adst = sbase + (arow*APH + seg)*2;

    int lt = lane >> 3, lrw = lane & 7;
    uint32_t aoff[2], boff[4];
    #pragma unroll
    for (int ma = 0; ma < 2; ma++) {
        int r = wm*32 + ma*16 + lrw + ((lt & 1) << 3);
        int kk = (lt >> 1) * 8;
        aoff[ma] = (uint32_t)((r*APH + kk) * 2);
    }
    #pragma unroll
    for (int g = 0; g < 4; g++) {
        int n = wn*64 + (g*2 + (lt >> 1))*8 + lrw;
        int kk = (lt & 1) * 8;
        boff[g] = (uint32_t)(CHH*2 + (n*APH + kk) * 2);
    }

    const int nc = K / 32;
    int asz = apred ? 16 : 0;

    auto issue = [&](int c){
        uint32_t off = (uint32_t)(c % NSTG) * 2*CHH*2;
        const __half* as = aptr + c*32;
        const __half* bs = bptr + c*32;
        cp16(adst + off,            as,     asz);
        cp16(adst + off + 16,       as + 8, asz);
        cp16(adst + off + CHH*2,      bs,     16);
        cp16(adst + off + CHH*2 + 16, bs + 8, 16);
        asm volatile("cp.async.commit_group;" ::: "memory");
    };

    issue(0); issue(1); issue(2); issue(3);
    for (int c = 0; c < nc; c++) {
        asm volatile("cp.async.wait_group 3;" ::: "memory");
        __syncthreads();
        if (c + 4 < nc) issue(c + 4);
        else asm volatile("cp.async.commit_group;" ::: "memory");  // keep group count
        uint32_t buf = sbase + (uint32_t)(c % NSTG)*2*CHH*2;
        #pragma unroll
        for (int ks = 0; ks < 2; ks++) {
            uint32_t kbb = ks*32;
            uint32_t af[2][4];
            #pragma unroll
            for (int ma = 0; ma < 2; ma++)
                ldsm4(af[ma], buf + aoff[ma] + kbb);
            uint32_t bf[8][2];
            #pragma unroll
            for (int g = 0; g < 4; g++) {
                uint32_t r4[4];
                ldsm4(r4, buf + boff[g] + kbb);
                bf[g*2  ][0] = r4[0]; bf[g*2  ][1] = r4[1];
                bf[g*2+1][0] = r4[2]; bf[g*2+1][1] = r4[3];
            }
            #pragma unroll
            for (int ma = 0; ma < 2; ma++)
                #pragma unroll
                for (int na = 0; na < 8; na++)
                    mma_f16(acc[ma][na], af[ma], bf[na]);
        }
    }

    #pragma unroll
    for (int ma = 0; ma < 2; ma++) {
        int r1 = row0 + wm*32 + ma*16 + lr;
        int r2 = r1 + 8;
        #pragma unroll
        for (int na = 0; na < 8; na++) {
            int col = col0 + wn*64 + na*8 + lc*2;
            float bx = bias[col], by = bias[col+1];
            float2 o1 = make_float2(acc[ma][na][0] + bx, acc[ma][na][1] + by);
            float2 o2 = make_float2(acc[ma][na][2] + bx, acc[ma][na][3] + by);
            if (relu) {
                o1.x = fmaxf(o1.x,0.f); o1.y = fmaxf(o1.y,0.f);
                o2.x = fmaxf(o2.x,0.f); o2.y = fmaxf(o2.y,0.f);
            }
            if (outf) {
                if (r1 < Nrows) *reinterpret_cast<float2*>(outf + (size_t)r1*NO + col) = o1;
                if (r2 < Nrows) *reinterpret_cast<float2*>(outf + (size_t)r2*NO + col) = o2;
            }
            if (outh) {
                if (r1 < Nrows)
                    *reinterpret_cast<__half2*>(outh + (size_t)r1*NO + col) = __floats2half2_rn(o1.x, o1.y);
                if (r2 < Nrows)
                    *reinterpret_cast<__half2*>(outh + (size_t)r2*NO + col) = __floats2half2_rn(o2.x, o2.y);
            }
        }
    }
}

// ============ preamble convert ============
__global__ void convert_pre_kernel(const float* __restrict__ ipts, const float* __restrict__ memory,
                                   __half* __restrict__ ipts_h, __half* __restrict__ mem_h,
                                   __half* __restrict__ tm_h)
{
    size_t i = (size_t)blockIdx.x*blockDim.x + threadIdx.x;
    size_t st = (size_t)gridDim.x*blockDim.x;
    const size_t ni = (size_t)Bc*Tc*Cc;
    const size_t nm = (size_t)Bc*Mc*Cc;
    for (size_t j = i; j < ni; j += st) ipts_h[j] = __float2half(ipts[j]);
    for (size_t j = i; j < nm; j += st) {
        float v = memory[j];
        mem_h[j] = __float2half(v);
        tm_h[j]  = __float2half(tanhf(v));
    }
}

// ============ batched transpose + half convert + bias concat ============
struct TPack {
    const float* in[6];
    __half* out[6];
    int C[6];
    const float* bk; const float* bv; float* bkv;
};
__global__ __launch_bounds__(256) void transpose_all_kernel(TPack p)
{
    __shared__ float t[32][33];
    int w = blockIdx.z;
    int C = p.C[w];
    int c0 = blockIdx.x*32;
    if (c0 >= C) return;
    int r0 = blockIdx.y*32;
    if (w == 0 && c0 == 0 && r0 == 0) {
        int i = threadIdx.x;
        p.bkv[i*2] = p.bk[i*2]; p.bkv[i*2+1] = p.bk[i*2+1];
        p.bkv[Cc + i*2] = p.bv[i*2]; p.bkv[Cc + i*2+1] = p.bv[i*2+1];
    }
    const float* in = p.in[w];
    __half* out = p.out[w];
    int x = threadIdx.x & 31, y = threadIdx.x >> 5;
    #pragma unroll
    for (int i = 0; i < 4; i++)
        t[y + i*8][x] = in[(size_t)(r0 + y + i*8)*C + c0 + x];
    __syncthreads();
    #pragma unroll
    for (int i = 0; i < 4; i++)
        out[(size_t)(c0 + y + i*8)*Cc + r0 + x] = __float2half(t[x][y + i*8]);
}

// ============ SIMT GEMM (tiny) ============
__global__ __launch_bounds__(256) void gemm_kernel(
    const float* __restrict__ A, const float* __restrict__ W,
    const float* __restrict__ bias, float* __restrict__ out,
    int N, int K, int NO, int relu)
{
    __shared__ float As[16][64];
    __shared__ float Bs[16][64];
    int t  = threadIdx.x;
    int tx = t & 15, ty = t >> 4;
    int row0 = blockIdx.y * 64;
    int col0 = blockIdx.x * 64;
    float acc[4][4] = {};
    for (int k0 = 0; k0 < K; k0 += 16) {
        {
            int r = t >> 2;
            int c4 = (t & 3) * 4;
            float4 av = make_float4(0.f,0.f,0.f,0.f);
            if (row0 + r < N)
                av = *reinterpret_cast<const float4*>(A + (size_t)(row0 + r) * K + k0 + c4);
            As[c4+0][r] = av.x; As[c4+1][r] = av.y; As[c4+2][r] = av.z; As[c4+3][r] = av.w;
        }
        {
            int r  = t >> 4;
            int c4 = (t & 15) * 4;
            float4 bv = *reinterpret_cast<const float4*>(W + (size_t)(k0 + r) * NO + col0 + c4);
            *reinterpret_cast<float4*>(&Bs[r][c4]) = bv;
        }
        __syncthreads();
        #pragma unroll
        for (int kk = 0; kk < 16; kk++) {
            float4 a4 = *reinterpret_cast<const float4*>(&As[kk][ty*4]);
            float4 b4 = *reinterpret_cast<const float4*>(&Bs[kk][tx*4]);
            float a[4] = {a4.x,a4.y,a4.z,a4.w};
            float b[4] = {b4.x,b4.y,b4.z,b4.w};
            #pragma unroll
            for (int i=0;i<4;i++)
                #pragma unroll
                for (int j=0;j<4;j++) acc[i][j] += a[i]*b[j];
        }
        __syncthreads();
    }
    float4 bb = *reinterpret_cast<const float4*>(bias + col0 + tx*4);
    #pragma unroll
    for (int i=0;i<4;i++) {
        int r = row0 + ty*4 + i;
        if (r >= N) continue;
        float4 o4;
        o4.x = acc[i][0] + bb.x; o4.y = acc[i][1] + bb.y;
        o4.z = acc[i][2] + bb.z; o4.w = acc[i][3] + bb.w;
        if (relu) {
            o4.x = fmaxf(o4.x,0.f); o4.y = fmaxf(o4.y,0.f);
            o4.z = fmaxf(o4.z,0.f); o4.w = fmaxf(o4.w,0.f);
        }
        *reinterpret_cast<float4*>(out + (size_t)r * NO + col0 + tx*4) = o4;
    }
}

// ============ warp reductions (x4-interleaved) ============
__device__ __forceinline__ void warpMax4(float* c){
    #pragma unroll
    for (int o=16;o;o>>=1){
        #pragma unroll
        for (int qq=0;qq<4;qq++) c[qq] = fmaxf(c[qq], __shfl_xor_sync(0xffffffffu, c[qq], o));
    }
}
__device__ __forceinline__ void warpSum4(float* c){
    #pragma unroll
    for (int o=16;o;o>>=1){
        #pragma unroll
        for (int qq=0;qq<4;qq++) c[qq] += __shfl_xor_sync(0xffffffffu, c[qq], o);
    }
}

// ============ top-k attention ============
#define Q_BLOCKS 6
#define SMEM_TOPK ((64*128 + 128*64 + 8*4*64)*4)
__global__ __launch_bounds__(256) void attn_topk_kernel(
    const float* __restrict__ q, const float* __restrict__ kv,
    float* __restrict__ o)
{
    extern __shared__ float sm[];
    float* Kt = sm;
    float* Vs = Kt + 64*128;
    float* sq = Vs + 128*64;

    int tid = threadIdx.x;
    int warp = tid >> 5, lane = tid & 31;
    int bh = blockIdx.x, b = bh / Hc, h = bh % Hc;

    for (int idx = tid; idx < 128*16; idx += 256) {
        int t = idx >> 4, j = idx & 15;
        size_t row = ((size_t)b*Tc + t)*KVS + h*64 + j*4;
        float4 kvv = *reinterpret_cast<const float4*>(kv + row);
        float4 vv  = *reinterpret_cast<const float4*>(kv + row + Cc);
        Kt[(j*4+0)*128 + t] = kvv.x;
        Kt[(j*4+1)*128 + t] = kvv.y;
        Kt[(j*4+2)*128 + t] = kvv.z;
        Kt[(j*4+3)*128 + t] = kvv.w;
        *reinterpret_cast<float4*>(&Vs[t*64 + j*4]) = vv;
    }
    __syncthreads();

    const int nq = (Mc + Q_BLOCKS - 1) / Q_BLOCKS;
    int q0 = blockIdx.y * nq;
    int qend = min(q0 + nq, Mc);
    float* sqw = sq + warp*256;

    for (int qi0 = q0 + warp*4; qi0 < qend; qi0 += 32) {
        #pragma unroll
        for (int f = 0; f < 2; f++) {
            int ff = lane + f*32;
            int qq = ff >> 4, j = ff & 15;
            int qi = qi0 + qq;
            if (qi < qend) {
                float4 qv = *reinterpret_cast<const float4*>(q + ((size_t)b*Mc + qi)*Cc + h*64 + j*4);
                *reinterpret_cast<float4*>(&sqw[qq*64 + j*4]) = qv;
            }
        }
        __syncwarp();
        float s[4][4];
        #pragma unroll
        for (int qq=0;qq<4;qq++)
            #pragma unroll
            for (int j=0;j<4;j++) s[qq][j] = 0.f;
        #pragma unroll 4
        for (int d0 = 0; d0 < 64; d0 += 4) {
            float4 kk4[4];
            #pragma unroll
            for (int dd = 0; dd < 4; dd++)
                kk4[dd] = *reinterpret_cast<const float4*>(&Kt[(d0+dd)*128 + lane*4]);
            #pragma unroll
            for (int qq = 0; qq < 4; qq++) {
                float4 qd = *reinterpret_cast<const float4*>(&sqw[qq*64 + d0]);
                s[qq][0] += qd.x*kk4[0].x + qd.y*kk4[1].x + qd.z*kk4[2].x + qd.w*kk4[3].x;
                s[qq][1] += qd.x*kk4[0].y + qd.y*kk4[1].y + qd.z*kk4[2].y + qd.w*kk4[3].y;
                s[qq][2] += qd.x*kk4[0].z + qd.y*kk4[1].z + qd.z*kk4[2].z + qd.w*kk4[3].z;
                s[qq][3] += qd.x*kk4[0].w + qd.y*kk4[1].w + qd.z*kk4[2].w + qd.w*kk4[3].w;
            }
        }
        #pragma unroll
        for (int qq=0;qq<4;qq++)
            #pragma unroll
            for (int j=0;j<4;j++) s[qq][j] *= 0.125f;

        float thr[4], gmax[4], c[4];
        #pragma unroll
        for (int qq=0;qq<4;qq++)
            c[qq] = fmaxf(fmaxf(s[qq][0],s[qq][1]), fmaxf(s[qq][2],s[qq][3]));
        warpMax4(c);
        #pragma unroll
        for (int qq=0;qq<4;qq++){ gmax[qq] = c[qq]; thr[qq] = c[qq]; }
        #pragma unroll
        for (int it = 1; it < TOPK; it++) {
            #pragma unroll
            for (int qq=0;qq<4;qq++){
                float m = -F_INF;
                #pragma unroll
                for (int j=0;j<4;j++) m = fmaxf(m, (s[qq][j] < thr[qq]) ? s[qq][j] : -F_INF);
                c[qq] = m;
            }
            warpMax4(c);
            #pragma unroll
            for (int qq=0;qq<4;qq++) thr[qq] = c[qq];
        }
        float e[4][4], le[4];
        #pragma unroll
        for (int qq=0;qq<4;qq++){
            le[qq] = 0.f;
            #pragma unroll
            for (int j=0;j<4;j++){ e[qq][j] = __expf(s[qq][j] - gmax[qq]); le[qq] += e[qq][j]; }
        }
        warpSum4(le);

        int d0v = lane*2;
        #pragma unroll
        for (int qq = 0; qq < 4; qq++) {
            int qi = qi0 + qq;
            if (qi >= qend) break;
            float inv = 1.f / le[qq];
            float p[4];
            #pragma unroll
            for (int j=0;j<4;j++) p[j] = (s[qq][j] >= thr[qq]) ? e[qq][j]*inv : 0.f;
            float2 acc = make_float2(0.f, 0.f);
            #pragma unroll
            for (int j=0;j<4;j++) {
                unsigned msk = __ballot_sync(0xffffffffu, p[j] != 0.f);
                while (msk) {
                    int src = __ffs(msk) - 1;
                    msk &= msk - 1;
                    float pv = __shfl_sync(0xffffffffu, p[j], src);
                    int key = src*4 + j;
                    float2 vv = *reinterpret_cast<const float2*>(&Vs[key*64 + d0v]);
                    acc.x += pv*vv.x; acc.y += pv*vv.y;
                }
            }
            *reinterpret_cast<float2*>(o + ((size_t)b*Mc + qi)*Cc + h*64 + d0v) = acc;
        }
    }
}

// ============ hx attention ============
#define SMEM_HX ((64*128 + 128*64 + 32*64 + 8*4*128)*4)
__global__ __launch_bounds__(256) void attn_hx_kernel(
    const float* __restrict__ q, const float* __restrict__ kv,
    float* __restrict__ o)
{
    extern __shared__ float sm[];
    float* Kt = sm;
    float* Vs = Kt + 64*128;
    float* sq = Vs + 128*64;
    float* ps = sq + 32*64;

    int tid = threadIdx.x;
    int warp = tid >> 5, lane = tid & 31;
    int bh = blockIdx.x, b = bh / Hc, h = bh % Hc;
    int q0 = blockIdx.y * 32;

    for (int idx = tid; idx < 32*16; idx += 256) {
        int qi = idx >> 4, j = idx & 15;
        float4 qv = *reinterpret_cast<const float4*>(q + ((size_t)b*Tc + q0 + qi)*Cc + h*64 + j*4);
        *reinterpret_cast<float4*>(&sq[qi*64 + j*4]) = qv;
    }

    float m[4], den[4];
    float2 acc[4];
    #pragma unroll
    for (int i=0;i<4;i++){ m[i] = -F_INF; den[i] = 0.f; acc[i] = make_float2(0.f,0.f); }
    int d0v = lane*2;
    float* psw = ps + warp*512;

    for (int c0 = 0; c0 < Mc; c0 += 128) {
        int nk = min(128, Mc - c0);
        __syncthreads();
        for (int idx = tid; idx < 128*16; idx += 256) {
            int t = idx >> 4, j = idx & 15;
            float4 kvv = make_float4(0.f,0.f,0.f,0.f), vv = kvv;
            if (t < nk) {
                size_t row = ((size_t)b*Mc + c0 + t)*KVS + h*64 + j*4;
                kvv = *reinterpret_cast<const float4*>(kv + row);
                vv  = *reinterpret_cast<const float4*>(kv + row + Cc);
            }
            Kt[(j*4+0)*128 + t] = kvv.x;
            Kt[(j*4+1)*128 + t] = kvv.y;
            Kt[(j*4+2)*128 + t] = kvv.z;
            Kt[(j*4+3)*128 + t] = kvv.w;
            *reinterpret_cast<float4*>(&Vs[t*64 + j*4]) = vv;
        }
        __syncthreads();

        float s[4][4];
        #pragma unroll
        for (int i=0;i<4;i++)
            #pragma unroll
            for (int j=0;j<4;j++) s[i][j] = 0.f;
        #pragma unroll 4
        for (int d0 = 0; d0 < 64; d0 += 4) {
            float4 kk4[4];
            #pragma unroll
            for (int dd = 0; dd < 4; dd++)
                kk4[dd] = *reinterpret_cast<const float4*>(&Kt[(d0+dd)*128 + lane*4]);
            #pragma unroll
            for (int i = 0; i < 4; i++) {
                float4 qd = *reinterpret_cast<const float4*>(&sq[(warp*4+i)*64 + d0]);
                s[i][0] += qd.x*kk4[0].x + qd.y*kk4[1].x + qd.z*kk4[2].x + qd.w*kk4[3].x;
                s[i][1] += qd.x*kk4[0].y + qd.y*kk4[1].y + qd.z*kk4[2].y + qd.w*kk4[3].y;
                s[i][2] += qd.x*kk4[0].z + qd.y*kk4[1].z + qd.z*kk4[2].z + qd.w*kk4[3].z;
                s[i][3] += qd.x*kk4[0].w + qd.y*kk4[1].w + qd.z*kk4[2].w + qd.w*kk4[3].w;
            }
        }
        float lm[4];
        #pragma unroll
        for (int i = 0; i < 4; i++) {
            float mm = -F_INF;
            #pragma unroll
            for (int j=0;j<4;j++) {
                s[i][j] = (lane*4 + j < nk) ? s[i][j]*0.125f : -F_INF;
                mm = fmaxf(mm, s[i][j]);
            }
            lm[i] = mm;
        }
        warpMax4(lm);
        float f[4], le[4];
        #pragma unroll
        for (int i = 0; i < 4; i++) {
            float newm = fmaxf(m[i], lm[i]);
            f[i] = __expf(m[i] - newm);
            m[i] = newm;
            float e0 = __expf(s[i][0]-newm), e1 = __expf(s[i][1]-newm);
            float e2 = __expf(s[i][2]-newm), e3 = __expf(s[i][3]-newm);
            le[i] = e0+e1+e2+e3;
            *reinterpret_cast<float4*>(&psw[i*128 + lane*4]) = make_float4(e0,e1,e2,e3);
        }
        warpSum4(le);
        #pragma unroll
        for (int i = 0; i < 4; i++) {
            den[i] = den[i]*f[i] + le[i];
            acc[i].x *= f[i]; acc[i].y *= f[i];
        }
        __syncwarp();
        #pragma unroll 4
        for (int kk = 0; kk < 128; kk++) {
            float2 vv = *reinterpret_cast<const float2*>(&Vs[kk*64 + d0v]);
            float p0 = psw[0*128 + kk], p1 = psw[1*128 + kk];
            float p2 = psw[2*128 + kk], p3 = psw[3*128 + kk];
            acc[0].x += p0*vv.x; acc[0].y += p0*vv.y;
            acc[1].x += p1*vv.x; acc[1].y += p1*vv.y;
            acc[2].x += p2*vv.x; acc[2].y += p2*vv.y;
            acc[3].x += p3*vv.x; acc[3].y += p3*vv.y;
        }
    }
    #pragma unroll
    for (int i=0;i<4;i++) {
        int qi = q0 + warp*4 + i;
        float invd = 1.f / den[i];
        float2 ov = make_float2(acc[i].x*invd, acc[i].y*invd);
        *reinterpret_cast<float2*>(o + ((size_t)b*Tc + qi)*Cc + h*64 + d0v) = ov;
    }
}

// ============ add + layernorm (float + half outputs) ============
__global__ __launch_bounds__(256) void add_ln_kernel(
    const float* __restrict__ x, const float* __restrict__ r,
    const float* __restrict__ g, const float* __restrict__ bb,
    float* __restrict__ out, __half* __restrict__ outh, int nrows)
{
    int warp = (blockIdx.x * blockDim.x + threadIdx.x) >> 5;
    int lane = threadIdx.x & 31;
    if (warp >= nrows) return;
    const float* xr = x + (size_t)warp * Cc;
    const float* rr = r + (size_t)warp * Cc;
    float vals[16];
    float s = 0.f;
    #pragma unroll
    for (int i=0;i<16;i++) { float vv = xr[lane + i*32] + rr[lane + i*32]; vals[i] = vv; s += vv; }
    #pragma unroll
    for (int o2=16;o2;o2>>=1) s += __shfl_xor_sync(0xffffffffu, s, o2);
    float mu = s * (1.f/512.f);
    float vs = 0.f;
    #pragma unroll
    for (int i=0;i<16;i++){ float d = vals[i]-mu; vs += d*d; }
    #pragma unroll
    for (int o2=16;o2;o2>>=1) vs += __shfl_xor_sync(0xffffffffu, vs, o2);
    float rstd = rsqrtf(vs*(1.f/512.f) + 1e-5f);
    float* outr = out + (size_t)warp * Cc;
    __half* outhr = outh + (size_t)warp * Cc;
    #pragma unroll
    for (int i=0;i<16;i++){
        int cc = lane + i*32;
        float ov = (vals[i]-mu)*rstd*g[cc] + bb[cc];
        outr[cc] = ov;
        outhr[cc] = __float2half(ov);
    }
}

// ============ misc elementwise ============
__global__ void repmean_kernel(const float* __restrict__ inp, const float* __restrict__ rep_w,
                               float* __restrict__ out)
{
    int b = blockIdx.x, c = threadIdx.x;
    const float* base = inp + (size_t)b*Tc*Cc + c;
    float rw = rep_w[c];
    float s = 0.f;
    for (int t=0;t<Tc;t++) s += fmaxf(rw * base[(size_t)t*Cc], 0.f);
    out[b*Cc + c] = s * (1.f/Tc);
}

__global__ void gate_kernel(const float* __restrict__ gates, const float* __restrict__ gi,
                            const float* __restrict__ mem_final, const float* __restrict__ mem0,
                            const float* __restrict__ ib, const float* __restrict__ fb,
                            float* __restrict__ nm, __half* __restrict__ nmh)
{
    size_t n = (size_t)Bc*Mc*Cc;
    size_t i = (size_t)blockIdx.x*blockDim.x + threadIdx.x;
    size_t st = (size_t)gridDim.x*blockDim.x;
    float ibv = ib[0], fbv = fb[0];
    for (; i < n; i += st) {
        int c = (int)(i % Cc);
        size_t bm = i / Cc;
        int b = (int)(bm / Mc);
        float gI = gates[bm*2*Cc + c]      + gi[b*2*Cc + c]      + ibv;
        float gF = gates[bm*2*Cc + Cc + c] + gi[b*2*Cc + Cc + c] + fbv;
        float igv = 1.f/(1.f + __expf(-gI));
        float fgv = 1.f/(1.f + __expf(-gF));
        float ov = igv * tanhf(mem_final[i]) + fgv * mem0[i];
        nm[i] = ov;
        nmh[i] = __float2half(ov);
    }
}

// ============ launch ============
extern "C" void kernel_launch(void* const* d_in, const int* in_sizes, int n_in,
                              void* d_out, int out_size)
{
    const float* ipts   = (const float*)d_in[0];
    const float* memory = (const float*)d_in[1];
    const float* Wq=(const float*)d_in[2],  *bq=(const float*)d_in[3];
    const float* Wk=(const float*)d_in[4],  *bk=(const float*)d_in[5];
    const float* Wv=(const float*)d_in[6],  *bv=(const float*)d_in[7];
    const float* Wm=(const float*)d_in[8],  *bm=(const float*)d_in[9];
    const float* g1=(const float*)d_in[10], *b1=(const float*)d_in[11];
    const float* g2=(const float*)d_in[12], *b2=(const float*)d_in[13];
    const float* Wp=(const float*)d_in[14], *bp=(const float*)d_in[15];
    const float* rep_w=(const float*)d_in[16];
    const float* Wig=(const float*)d_in[17], *big=(const float*)d_in[18];
    const float* Wmg=(const float*)d_in[19], *bmg=(const float*)d_in[20];
    const float* fb=(const float*)d_in[21], *ib=(const float*)d_in[22];

    float* out_nm = (float*)d_out;
    float* out_hx = out_nm + (size_t)Bc*Mc*Cc;

    float *inp,*mem,*qb,*kvs,*ao,*h2,*gt,*rm,*gi,*bkv;
    __half *ipts_h,*inp_h,*mem_h,*h1_h,*tm_h,*nm_h;
    __half *WqT,*WkvT,*WmT,*WpT,*WmgT;
    cudaGetSymbolAddress((void**)&inp, d_inp);
    cudaGetSymbolAddress((void**)&mem, d_mem);
    cudaGetSymbolAddress((void**)&qb,  d_qb);
    cudaGetSymbolAddress((void**)&kvs, d_kvs);
    cudaGetSymbolAddress((void**)&ao,  d_ao);
    cudaGetSymbolAddress((void**)&h2,  d_h2);
    cudaGetSymbolAddress((void**)&gt,  d_gt);
    cudaGetSymbolAddress((void**)&rm,  d_rm);
    cudaGetSymbolAddress((void**)&gi,  d_gi);
    cudaGetSymbolAddress((void**)&bkv, d_bkv);
    cudaGetSymbolAddress((void**)&ipts_h, d_ipts_h);
    cudaGetSymbolAddress((void**)&inp_h,  d_inp_h);
    cudaGetSymbolAddress((void**)&mem_h,  d_mem_h);
    cudaGetSymbolAddress((void**)&h1_h,   d_h1_h);
    cudaGetSymbolAddress((void**)&tm_h,   d_tm_h);
    cudaGetSymbolAddress((void**)&nm_h,   d_nm_h);
    cudaGetSymbolAddress((void**)&WqT, d_WqT);
    cudaGetSymbolAddress((void**)&WkvT, d_WkvT);
    cudaGetSymbolAddress((void**)&WmT, d_WmT);
    cudaGetSymbolAddress((void**)&WpT, d_WpT);
    cudaGetSymbolAddress((void**)&WmgT, d_WmgT);

    cudaFuncSetAttribute(attn_topk_kernel, cudaFuncAttributeMaxDynamicSharedMemorySize, SMEM_TOPK);
    cudaFuncSetAttribute(attn_hx_kernel,   cudaFuncAttributeMaxDynamicSharedMemorySize, SMEM_HX);
    cudaFuncSetAttribute(f16_gemm_kernel,  cudaFuncAttributeMaxDynamicSharedMemorySize, TG_SMEM);

    TPack tp;
    tp.in[0]=Wq;  tp.out[0]=WqT;           tp.C[0]=Cc;
    tp.in[1]=Wk;  tp.out[1]=WkvT;          tp.C[1]=Cc;
    tp.in[2]=Wv;  tp.out[2]=WkvT + Cc*Cc;  tp.C[2]=Cc;
    tp.in[3]=Wm;  tp.out[3]=WmT;           tp.C[3]=Cc;
    tp.in[4]=Wp;  tp.out[4]=WpT;           tp.C[4]=Cc;
    tp.in[5]=Wmg; tp.out[5]=WmgT;          tp.C[5]=2*Cc;
    tp.bk = bk; tp.bv = bv; tp.bkv = bkv;
    transpose_all_kernel<<<dim3(32,16,6), 256>>>(tp);
    convert_pre_kernel<<<2048, 256>>>(ipts, memory, ipts_h, mem_h, tm_h);

    auto tgemm = [&](const __half* A, const __half* WT, const float* bias,
                     float* of, __half* oh, int N, int NO, int relu){
        f16_gemm_kernel<<<dim3(NO/128, (N+127)/128), 256, TG_SMEM>>>(
            A, WT, bias, of, oh, N, Cc, NO, relu);
    };

    // inp = ipts @ Wp + bp (float + half); fused k|v from inp_h
    tgemm(ipts_h, WpT, bp, inp, inp_h, Bc*Tc, Cc, 0);
    tgemm(inp_h, WkvT, bkv, kvs, nullptr, Bc*Tc, KVS, 0);

    for (int blk = 0; blk < NBLK; blk++) {
        tgemm(mem_h, WqT, bq, qb, nullptr, Bc*Mc, Cc, 0);
        attn_topk_kernel<<<dim3(Bc*Hc, Q_BLOCKS), 256, SMEM_TOPK>>>(qb, kvs, ao);
        const float* xres = (blk == 0) ? memory : mem;
        add_ln_kernel<<<(Bc*Mc + 7)/8, 256>>>(xres, ao, g1, b1, mem, mem_h, Bc*Mc);
        tgemm(mem_h, WmT, bm, nullptr, h1_h, Bc*Mc, Cc, 1);
        tgemm(h1_h,  WmT, bm, h2, nullptr, Bc*Mc, Cc, 1);
        add_ln_kernel<<<(Bc*Mc + 7)/8, 256>>>(mem, h2, g2, b2, mem, mem_h, Bc*Mc);
    }

    // gates
    repmean_kernel<<<Bc, Cc>>>(inp, rep_w, rm);
    gemm_kernel<<<dim3(2*Cc/64, 1), 256>>>(rm, Wig, big, gi, Bc, Cc, 2*Cc, 0);
    tgemm(tm_h, WmgT, bmg, gt, nullptr, Bc*Mc, 2*Cc, 0);
    gate_kernel<<<2048, 256>>>(gt, gi, mem, memory, ib, fb, out_nm, nm_h);

    // hx
    tgemm(inp_h, WqT, bq, qb, nullptr, Bc*Tc, Cc, 0);
    tgemm(nm_h, WkvT, bkv, gt, nullptr, Bc*Mc, KVS, 0);
    attn_hx_kernel<<<dim3(Bc*Hc, Tc/32), 256, SMEM_HX>>>(qb, gt, out_hx);
}

// round 17
// speedup vs baseline: 1.2103x; 1.1414x over previous
#include <cuda_runtime.h>
#include <cuda_fp16.h>
#include <math.h>
#include <stdint.h>

#define Bc 32
#define Tc 128
#define Mc 1290
#define Cc 512
#define Hc 8
#define NBLK 4
#define TOPK 8
#define KVS 1024

static __device__ float d_inp[Bc*Tc*Cc];
static __device__ float d_mem[(size_t)Bc*Mc*Cc];
static __device__ float d_qb [(size_t)Bc*Mc*Cc];
static __device__ float d_kvs[(size_t)Bc*Tc*KVS];
static __device__ float d_gt [(size_t)Bc*Mc*2*Cc];   // kv_big float; gate logits stored as half in-place
static __device__ float d_rm [Bc*Cc];
static __device__ float d_gi [Bc*2*Cc];
static __device__ float d_bkv[2*Cc];
// half intermediates
static __device__ __half d_ao_h[(size_t)Bc*Mc*Cc];
static __device__ __half d_h2_h[(size_t)Bc*Mc*Cc];
// half activation mirrors
static __device__ __half d_ipts_h[Bc*Tc*Cc];
static __device__ __half d_inp_h [Bc*Tc*Cc];
static __device__ __half d_mem_h [(size_t)Bc*Mc*Cc];
static __device__ __half d_h1_h  [(size_t)Bc*Mc*Cc];
static __device__ __half d_tm_h  [(size_t)Bc*Mc*Cc];
static __device__ __half d_nm_h  [(size_t)Bc*Mc*Cc];
// half weights (K-major)
static __device__ __half d_WqT[Cc*Cc];
static __device__ __half d_WkvT[2*Cc*Cc];
static __device__ __half d_WmT[Cc*Cc];
static __device__ __half d_WpT[Cc*Cc];
static __device__ __half d_WmgT[Cc*2*Cc];

#define F_INF __int_as_float(0x7f800000)

__device__ __forceinline__ uint32_t smem_u32(const void* p){
    uint32_t a;
    asm("{ .reg .u64 t; cvta.to.shared.u64 t, %1; cvt.u32.u64 %0, t; }" : "=r"(a) : "l"(p));
    return a;
}
__device__ __forceinline__ void mma_f16(float* d, const uint32_t* a, const uint32_t* b){
    asm volatile("mma.sync.aligned.m16n8k16.row.col.f32.f16.f16.f32 "
        "{%0,%1,%2,%3}, {%4,%5,%6,%7}, {%8,%9}, {%0,%1,%2,%3};"
        : "+f"(d[0]), "+f"(d[1]), "+f"(d[2]), "+f"(d[3])
        : "r"(a[0]), "r"(a[1]), "r"(a[2]), "r"(a[3]), "r"(b[0]), "r"(b[1]));
}
__device__ __forceinline__ void ldsm4(uint32_t* r, uint32_t addr){
    asm volatile("ldmatrix.sync.aligned.m8n8.x4.shared.b16 {%0,%1,%2,%3}, [%4];"
        : "=r"(r[0]), "=r"(r[1]), "=r"(r[2]), "=r"(r[3]) : "r"(addr));
}
__device__ __forceinline__ void cp16(uint32_t dst, const void* src, int sz){
    asm volatile("cp.async.ca.shared.global [%0], [%1], 16, %2;"
                 :: "r"(dst), "l"(src), "r"(sz) : "memory");
}

// ============ all-half GEMM (R14 config): 128x128 tile, K-chunk 32, 4-stage cp.async ============
#define APH 40
#define CHH (128*APH)
#define NSTG 4
#define TG_SMEM (NSTG*2*CHH*2)
__global__ __launch_bounds__(256) void f16_gemm_kernel(
    const __half* __restrict__ A, const __half* __restrict__ WT,
    const float* __restrict__ bias, float* __restrict__ outf,
    __half* __restrict__ outh,
    int Nrows, int K, int NO, int relu)
{
    extern __shared__ __half smh[];
    int tid = threadIdx.x;
    int wid = tid >> 5, lane = tid & 31;
    int wm = wid & 3, wn = wid >> 2;
    int lr = lane >> 2, lc = lane & 3;
    int row0 = blockIdx.y * 128;
    int col0 = blockIdx.x * 128;

    float acc[2][8][4];
    #pragma unroll
    for (int i=0;i<2;i++)
        #pragma unroll
        for (int j=0;j<8;j++)
            #pragma unroll
            for (int l=0;l<4;l++) acc[i][j][l] = 0.f;

    int arow = tid & 127;
    int seg  = (tid >> 7) * 16;
    bool apred = (row0 + arow) < Nrows;
    const __half* aptr = A  + (size_t)(row0 + arow)*K + seg;
    const __half* bptr = WT + (size_t)(col0 + arow)*K + seg;
    uint32_t sbase = smem_u32(smh);
    uint32_t adst = sbase + (arow*APH + seg)*2;

    int lt = lane >> 3, lrw = lane & 7;
    uint32_t aoff[2], boff[4];
    #pragma unroll
    for (int ma = 0; ma < 2; ma++) {
        int r = wm*32 + ma*16 + lrw + ((lt & 1) << 3);
        int kk = (lt >> 1) * 8;
        aoff[ma] = (uint32_t)((r*APH + kk) * 2);
    }
    #pragma unroll
    for (int g = 0; g < 4; g++) {
        int n = wn*64 + (g*2 + (lt >> 1))*8 + lrw;
        int kk = (lt & 1) * 8;
        boff[g] = (uint32_t)(CHH*2 + (n*APH + kk) * 2);
    }

    const int nc = K / 32;
    int asz = apred ? 16 : 0;

    auto issue = [&](int c){
        uint32_t off = (uint32_t)(c & (NSTG-1)) * 2*CHH*2;
        const __half* as = aptr + c*32;
        const __half* bs = bptr + c*32;
        cp16(adst + off,            as,     asz);
        cp16(adst + off + 16,       as + 8, asz);
        cp16(adst + off + CHH*2,      bs,     16);
        cp16(adst + off + CHH*2 + 16, bs + 8, 16);
        asm volatile("cp.async.commit_group;" ::: "memory");
    };

    issue(0); issue(1); issue(2);
    for (int c = 0; c < nc; c++) {
        asm volatile("cp.async.wait_group 2;" ::: "memory");
        __syncthreads();
        if (c + 3 < nc) issue(c + 3);
        else asm volatile("cp.async.commit_group;" ::: "memory");  // keep group count
        uint32_t buf = sbase + (uint32_t)(c & (NSTG-1))*2*CHH*2;
        #pragma unroll
        for (int ks = 0; ks < 2; ks++) {
            uint32_t kbb = ks*32;
            uint32_t af[2][4];
            #pragma unroll
            for (int ma = 0; ma < 2; ma++)
                ldsm4(af[ma], buf + aoff[ma] + kbb);
            uint32_t bf[8][2];
            #pragma unroll
            for (int g = 0; g < 4; g++) {
                uint32_t r4[4];
                ldsm4(r4, buf + boff[g] + kbb);
                bf[g*2  ][0] = r4[0]; bf[g*2  ][1] = r4[1];
                bf[g*2+1][0] = r4[2]; bf[g*2+1][1] = r4[3];
            }
            #pragma unroll
            for (int ma = 0; ma < 2; ma++)
                #pragma unroll
                for (int na = 0; na < 8; na++)
                    mma_f16(acc[ma][na], af[ma], bf[na]);
        }
    }

    #pragma unroll
    for (int ma = 0; ma < 2; ma++) {
        int r1 = row0 + wm*32 + ma*16 + lr;
        int r2 = r1 + 8;
        #pragma unroll
        for (int na = 0; na < 8; na++) {
            int col = col0 + wn*64 + na*8 + lc*2;
            float bx = bias[col], by = bias[col+1];
            float2 o1 = make_float2(acc[ma][na][0] + bx, acc[ma][na][1] + by);
            float2 o2 = make_float2(acc[ma][na][2] + bx, acc[ma][na][3] + by);
            if (relu) {
                o1.x = fmaxf(o1.x,0.f); o1.y = fmaxf(o1.y,0.f);
                o2.x = fmaxf(o2.x,0.f); o2.y = fmaxf(o2.y,0.f);
            }
            if (outf) {
                if (r1 < Nrows) *reinterpret_cast<float2*>(outf + (size_t)r1*NO + col) = o1;
                if (r2 < Nrows) *reinterpret_cast<float2*>(outf + (size_t)r2*NO + col) = o2;
            }
            if (outh) {
                if (r1 < Nrows)
                    *reinterpret_cast<__half2*>(outh + (size_t)r1*NO + col) = __floats2half2_rn(o1.x, o1.y);
                if (r2 < Nrows)
                    *reinterpret_cast<__half2*>(outh + (size_t)r2*NO + col) = __floats2half2_rn(o2.x, o2.y);
            }
        }
    }
}

// ============ preamble convert ============
__global__ void convert_pre_kernel(const float* __restrict__ ipts, const float* __restrict__ memory,
                                   __half* __restrict__ ipts_h, __half* __restrict__ mem_h,
                                   __half* __restrict__ tm_h)
{
    size_t i = (size_t)blockIdx.x*blockDim.x + threadIdx.x;
    size_t st = (size_t)gridDim.x*blockDim.x;
    const size_t ni = (size_t)Bc*Tc*Cc;
    const size_t nm = (size_t)Bc*Mc*Cc;
    for (size_t j = i; j < ni; j += st) ipts_h[j] = __float2half(ipts[j]);
    for (size_t j = i; j < nm; j += st) {
        float v = memory[j];
        mem_h[j] = __float2half(v);
        tm_h[j]  = __float2half(tanhf(v));
    }
}

// ============ batched transpose + half convert + bias concat ============
struct TPack {
    const float* in[6];
    __half* out[6];
    int C[6];
    const float* bk; const float* bv; float* bkv;
};
__global__ __launch_bounds__(256) void transpose_all_kernel(TPack p)
{
    __shared__ float t[32][33];
    int w = blockIdx.z;
    int C = p.C[w];
    int c0 = blockIdx.x*32;
    if (c0 >= C) return;
    int r0 = blockIdx.y*32;
    if (w == 0 && c0 == 0 && r0 == 0) {
        int i = threadIdx.x;
        p.bkv[i*2] = p.bk[i*2]; p.bkv[i*2+1] = p.bk[i*2+1];
        p.bkv[Cc + i*2] = p.bv[i*2]; p.bkv[Cc + i*2+1] = p.bv[i*2+1];
    }
    const float* in = p.in[w];
    __half* out = p.out[w];
    int x = threadIdx.x & 31, y = threadIdx.x >> 5;
    #pragma unroll
    for (int i = 0; i < 4; i++)
        t[y + i*8][x] = in[(size_t)(r0 + y + i*8)*C + c0 + x];
    __syncthreads();
    #pragma unroll
    for (int i = 0; i < 4; i++)
        out[(size_t)(c0 + y + i*8)*Cc + r0 + x] = __float2half(t[x][y + i*8]);
}

// ============ SIMT GEMM (tiny) ============
__global__ __launch_bounds__(256) void gemm_kernel(
    const float* __restrict__ A, const float* __restrict__ W,
    const float* __restrict__ bias, float* __restrict__ out,
    int N, int K, int NO, int relu)
{
    __shared__ float As[16][64];
    __shared__ float Bs[16][64];
    int t  = threadIdx.x;
    int tx = t & 15, ty = t >> 4;
    int row0 = blockIdx.y * 64;
    int col0 = blockIdx.x * 64;
    float acc[4][4] = {};
    for (int k0 = 0; k0 < K; k0 += 16) {
        {
            int r = t >> 2;
            int c4 = (t & 3) * 4;
            float4 av = make_float4(0.f,0.f,0.f,0.f);
            if (row0 + r < N)
                av = *reinterpret_cast<const float4*>(A + (size_t)(row0 + r) * K + k0 + c4);
            As[c4+0][r] = av.x; As[c4+1][r] = av.y; As[c4+2][r] = av.z; As[c4+3][r] = av.w;
        }
        {
            int r  = t >> 4;
            int c4 = (t & 15) * 4;
            float4 bv = *reinterpret_cast<const float4*>(W + (size_t)(k0 + r) * NO + col0 + c4);
            *reinterpret_cast<float4*>(&Bs[r][c4]) = bv;
        }
        __syncthreads();
        #pragma unroll
        for (int kk = 0; kk < 16; kk++) {
            float4 a4 = *reinterpret_cast<const float4*>(&As[kk][ty*4]);
            float4 b4 = *reinterpret_cast<const float4*>(&Bs[kk][tx*4]);
            float a[4] = {a4.x,a4.y,a4.z,a4.w};
            float b[4] = {b4.x,b4.y,b4.z,b4.w};
            #pragma unroll
            for (int i=0;i<4;i++)
                #pragma unroll
                for (int j=0;j<4;j++) acc[i][j] += a[i]*b[j];
        }
        __syncthreads();
    }
    float4 bb = *reinterpret_cast<const float4*>(bias + col0 + tx*4);
    #pragma unroll
    for (int i=0;i<4;i++) {
        int r = row0 + ty*4 + i;
        if (r >= N) continue;
        float4 o4;
        o4.x = acc[i][0] + bb.x; o4.y = acc[i][1] + bb.y;
        o4.z = acc[i][2] + bb.z; o4.w = acc[i][3] + bb.w;
        if (relu) {
            o4.x = fmaxf(o4.x,0.f); o4.y = fmaxf(o4.y,0.f);
            o4.z = fmaxf(o4.z,0.f); o4.w = fmaxf(o4.w,0.f);
        }
        *reinterpret_cast<float4*>(out + (size_t)r * NO + col0 + tx*4) = o4;
    }
}

// ============ warp reductions (x4-interleaved) ============
__device__ __forceinline__ void warpMax4(float* c){
    #pragma unroll
    for (int o=16;o;o>>=1){
        #pragma unroll
        for (int qq=0;qq<4;qq++) c[qq] = fmaxf(c[qq], __shfl_xor_sync(0xffffffffu, c[qq], o));
    }
}
__device__ __forceinline__ void warpSum4(float* c){
    #pragma unroll
    for (int o=16;o;o>>=1){
        #pragma unroll
        for (int qq=0;qq<4;qq++) c[qq] += __shfl_xor_sync(0xffffffffu, c[qq], o);
    }
}

// ============ top-k attention (half output) ============
#define Q_BLOCKS 6
#define SMEM_TOPK ((64*128 + 128*64 + 8*4*64)*4)
__global__ __launch_bounds__(256) void attn_topk_kernel(
    const float* __restrict__ q, const float* __restrict__ kv,
    __half* __restrict__ o)
{
    extern __shared__ float sm[];
    float* Kt = sm;
    float* Vs = Kt + 64*128;
    float* sq = Vs + 128*64;

    int tid = threadIdx.x;
    int warp = tid >> 5, lane = tid & 31;
    int bh = blockIdx.x, b = bh / Hc, h = bh % Hc;

    for (int idx = tid; idx < 128*16; idx += 256) {
        int t = idx >> 4, j = idx & 15;
        size_t row = ((size_t)b*Tc + t)*KVS + h*64 + j*4;
        float4 kvv = *reinterpret_cast<const float4*>(kv + row);
        float4 vv  = *reinterpret_cast<const float4*>(kv + row + Cc);
        Kt[(j*4+0)*128 + t] = kvv.x;
        Kt[(j*4+1)*128 + t] = kvv.y;
        Kt[(j*4+2)*128 + t] = kvv.z;
        Kt[(j*4+3)*128 + t] = kvv.w;
        *reinterpret_cast<float4*>(&Vs[t*64 + j*4]) = vv;
    }
    __syncthreads();

    const int nq = (Mc + Q_BLOCKS - 1) / Q_BLOCKS;
    int q0 = blockIdx.y * nq;
    int qend = min(q0 + nq, Mc);
    float* sqw = sq + warp*256;

    for (int qi0 = q0 + warp*4; qi0 < qend; qi0 += 32) {
        #pragma unroll
        for (int f = 0; f < 2; f++) {
            int ff = lane + f*32;
            int qq = ff >> 4, j = ff & 15;
            int qi = qi0 + qq;
            if (qi < qend) {
                float4 qv = *reinterpret_cast<const float4*>(q + ((size_t)b*Mc + qi)*Cc + h*64 + j*4);
                *reinterpret_cast<float4*>(&sqw[qq*64 + j*4]) = qv;
            }
        }
        __syncwarp();
        float s[4][4];
        #pragma unroll
        for (int qq=0;qq<4;qq++)
            #pragma unroll
            for (int j=0;j<4;j++) s[qq][j] = 0.f;
        #pragma unroll 4
        for (int d0 = 0; d0 < 64; d0 += 4) {
            float4 kk4[4];
            #pragma unroll
            for (int dd = 0; dd < 4; dd++)
                kk4[dd] = *reinterpret_cast<const float4*>(&Kt[(d0+dd)*128 + lane*4]);
            #pragma unroll
            for (int qq = 0; qq < 4; qq++) {
                float4 qd = *reinterpret_cast<const float4*>(&sqw[qq*64 + d0]);
                s[qq][0] += qd.x*kk4[0].x + qd.y*kk4[1].x + qd.z*kk4[2].x + qd.w*kk4[3].x;
                s[qq][1] += qd.x*kk4[0].y + qd.y*kk4[1].y + qd.z*kk4[2].y + qd.w*kk4[3].y;
                s[qq][2] += qd.x*kk4[0].z + qd.y*kk4[1].z + qd.z*kk4[2].z + qd.w*kk4[3].z;
                s[qq][3] += qd.x*kk4[0].w + qd.y*kk4[1].w + qd.z*kk4[2].w + qd.w*kk4[3].w;
            }
        }
        #pragma unroll
        for (int qq=0;qq<4;qq++)
            #pragma unroll
            for (int j=0;j<4;j++) s[qq][j] *= 0.125f;

        float thr[4], gmax[4], c[4];
        #pragma unroll
        for (int qq=0;qq<4;qq++)
            c[qq] = fmaxf(fmaxf(s[qq][0],s[qq][1]), fmaxf(s[qq][2],s[qq][3]));
        warpMax4(c);
        #pragma unroll
        for (int qq=0;qq<4;qq++){ gmax[qq] = c[qq]; thr[qq] = c[qq]; }
        #pragma unroll
        for (int it = 1; it < TOPK; it++) {
            #pragma unroll
            for (int qq=0;qq<4;qq++){
                float m = -F_INF;
                #pragma unroll
                for (int j=0;j<4;j++) m = fmaxf(m, (s[qq][j] < thr[qq]) ? s[qq][j] : -F_INF);
                c[qq] = m;
            }
            warpMax4(c);
            #pragma unroll
            for (int qq=0;qq<4;qq++) thr[qq] = c[qq];
        }
        float e[4][4], le[4];
        #pragma unroll
        for (int qq=0;qq<4;qq++){
            le[qq] = 0.f;
            #pragma unroll
            for (int j=0;j<4;j++){ e[qq][j] = __expf(s[qq][j] - gmax[qq]); le[qq] += e[qq][j]; }
        }
        warpSum4(le);

        int d0v = lane*2;
        #pragma unroll
        for (int qq = 0; qq < 4; qq++) {
            int qi = qi0 + qq;
            if (qi >= qend) break;
            float inv = 1.f / le[qq];
            float p[4];
            #pragma unroll
            for (int j=0;j<4;j++) p[j] = (s[qq][j] >= thr[qq]) ? e[qq][j]*inv : 0.f;
            float2 acc = make_float2(0.f, 0.f);
            #pragma unroll
            for (int j=0;j<4;j++) {
                unsigned msk = __ballot_sync(0xffffffffu, p[j] != 0.f);
                while (msk) {
                    int src = __ffs(msk) - 1;
                    msk &= msk - 1;
                    float pv = __shfl_sync(0xffffffffu, p[j], src);
                    int key = src*4 + j;
                    float2 vv = *reinterpret_cast<const float2*>(&Vs[key*64 + d0v]);
                    acc.x += pv*vv.x; acc.y += pv*vv.y;
                }
            }
            *reinterpret_cast<__half2*>(o + ((size_t)b*Mc + qi)*Cc + h*64 + d0v) =
                __floats2half2_rn(acc.x, acc.y);
        }
    }
}

// ============ hx attention (float output: final) ============
#define SMEM_HX ((64*128 + 128*64 + 32*64 + 8*4*128)*4)
__global__ __launch_bounds__(256) void attn_hx_kernel(
    const float* __restrict__ q, const float* __restrict__ kv,
    float* __restrict__ o)
{
    extern __shared__ float sm[];
    float* Kt = sm;
    float* Vs = Kt + 64*128;
    float* sq = Vs + 128*64;
    float* ps = sq + 32*64;

    int tid = threadIdx.x;
    int warp = tid >> 5, lane = tid & 31;
    int bh = blockIdx.x, b = bh / Hc, h = bh % Hc;
    int q0 = blockIdx.y * 32;

    for (int idx = tid; idx < 32*16; idx += 256) {
        int qi = idx >> 4, j = idx & 15;
        float4 qv = *reinterpret_cast<const float4*>(q + ((size_t)b*Tc + q0 + qi)*Cc + h*64 + j*4);
        *reinterpret_cast<float4*>(&sq[qi*64 + j*4]) = qv;
    }

    float m[4], den[4];
    float2 acc[4];
    #pragma unroll
    for (int i=0;i<4;i++){ m[i] = -F_INF; den[i] = 0.f; acc[i] = make_float2(0.f,0.f); }
    int d0v = lane*2;
    float* psw = ps + warp*512;

    for (int c0 = 0; c0 < Mc; c0 += 128) {
        int nk = min(128, Mc - c0);
        __syncthreads();
        for (int idx = tid; idx < 128*16; idx += 256) {
            int t = idx >> 4, j = idx & 15;
            float4 kvv = make_float4(0.f,0.f,0.f,0.f), vv = kvv;
            if (t < nk) {
                size_t row = ((size_t)b*Mc + c0 + t)*KVS + h*64 + j*4;
                kvv = *reinterpret_cast<const float4*>(kv + row);
                vv  = *reinterpret_cast<const float4*>(kv + row + Cc);
            }
            Kt[(j*4+0)*128 + t] = kvv.x;
            Kt[(j*4+1)*128 + t] = kvv.y;
            Kt[(j*4+2)*128 + t] = kvv.z;
            Kt[(j*4+3)*128 + t] = kvv.w;
            *reinterpret_cast<float4*>(&Vs[t*64 + j*4]) = vv;
        }
        __syncthreads();

        float s[4][4];
        #pragma unroll
        for (int i=0;i<4;i++)
            #pragma unroll
            for (int j=0;j<4;j++) s[i][j] = 0.f;
        #pragma unroll 4
        for (int d0 = 0; d0 < 64; d0 += 4) {
            float4 kk4[4];
            #pragma unroll
            for (int dd = 0; dd < 4; dd++)
                kk4[dd] = *reinterpret_cast<const float4*>(&Kt[(d0+dd)*128 + lane*4]);
            #pragma unroll
            for (int i = 0; i < 4; i++) {
                float4 qd = *reinterpret_cast<const float4*>(&sq[(warp*4+i)*64 + d0]);
                s[i][0] += qd.x*kk4[0].x + qd.y*kk4[1].x + qd.z*kk4[2].x + qd.w*kk4[3].x;
                s[i][1] += qd.x*kk4[0].y + qd.y*kk4[1].y + qd.z*kk4[2].y + qd.w*kk4[3].y;
                s[i][2] += qd.x*kk4[0].z + qd.y*kk4[1].z + qd.z*kk4[2].z + qd.w*kk4[3].z;
                s[i][3] += qd.x*kk4[0].w + qd.y*kk4[1].w + qd.z*kk4[2].w + qd.w*kk4[3].w;
            }
        }
        float lm[4];
        #pragma unroll
        for (int i = 0; i < 4; i++) {
            float mm = -F_INF;
            #pragma unroll
            for (int j=0;j<4;j++) {
                s[i][j] = (lane*4 + j < nk) ? s[i][j]*0.125f : -F_INF;
                mm = fmaxf(mm, s[i][j]);
            }
            lm[i] = mm;
        }
        warpMax4(lm);
        float f[4], le[4];
        #pragma unroll
        for (int i = 0; i < 4; i++) {
            float newm = fmaxf(m[i], lm[i]);
            f[i] = __expf(m[i] - newm);
            m[i] = newm;
            float e0 = __expf(s[i][0]-newm), e1 = __expf(s[i][1]-newm);
            float e2 = __expf(s[i][2]-newm), e3 = __expf(s[i][3]-newm);
            le[i] = e0+e1+e2+e3;
            *reinterpret_cast<float4*>(&psw[i*128 + lane*4]) = make_float4(e0,e1,e2,e3);
        }
        warpSum4(le);
        #pragma unroll
        for (int i = 0; i < 4; i++) {
            den[i] = den[i]*f[i] + le[i];
            acc[i].x *= f[i]; acc[i].y *= f[i];
        }
        __syncwarp();
        #pragma unroll 4
        for (int kk = 0; kk < 128; kk++) {
            float2 vv = *reinterpret_cast<const float2*>(&Vs[kk*64 + d0v]);
            float p0 = psw[0*128 + kk], p1 = psw[1*128 + kk];
            float p2 = psw[2*128 + kk], p3 = psw[3*128 + kk];
            acc[0].x += p0*vv.x; acc[0].y += p0*vv.y;
            acc[1].x += p1*vv.x; acc[1].y += p1*vv.y;
            acc[2].x += p2*vv.x; acc[2].y += p2*vv.y;
            acc[3].x += p3*vv.x; acc[3].y += p3*vv.y;
        }
    }
    #pragma unroll
    for (int i=0;i<4;i++) {
        int qi = q0 + warp*4 + i;
        float invd = 1.f / den[i];
        float2 ov = make_float2(acc[i].x*invd, acc[i].y*invd);
        *reinterpret_cast<float2*>(o + ((size_t)b*Tc + qi)*Cc + h*64 + d0v) = ov;
    }
}

// ============ add + layernorm: residual float + half r-input ============
__global__ __launch_bounds__(256) void add_ln_kernel(
    const float* __restrict__ x, const __half* __restrict__ r,
    const float* __restrict__ g, const float* __restrict__ bb,
    float* __restrict__ out, __half* __restrict__ outh, int nrows)
{
    int warp = (blockIdx.x * blockDim.x + threadIdx.x) >> 5;
    int lane = threadIdx.x & 31;
    if (warp >= nrows) return;
    const float* xr = x + (size_t)warp * Cc;
    const __half* rr = r + (size_t)warp * Cc;
    float vals[16];
    float s = 0.f;
    #pragma unroll
    for (int i=0;i<16;i++) {
        float vv = xr[lane + i*32] + __half2float(rr[lane + i*32]);
        vals[i] = vv; s += vv;
    }
    #pragma unroll
    for (int o2=16;o2;o2>>=1) s += __shfl_xor_sync(0xffffffffu, s, o2);
    float mu = s * (1.f/512.f);
    float vs = 0.f;
    #pragma unroll
    for (int i=0;i<16;i++){ float d = vals[i]-mu; vs += d*d; }
    #pragma unroll
    for (int o2=16;o2;o2>>=1) vs += __shfl_xor_sync(0xffffffffu, vs, o2);
    float rstd = rsqrtf(vs*(1.f/512.f) + 1e-5f);
    float* outr = out + (size_t)warp * Cc;
    __half* outhr = outh + (size_t)warp * Cc;
    #pragma unroll
    for (int i=0;i<16;i++){
        int cc = lane + i*32;
        float ov = (vals[i]-mu)*rstd*g[cc] + bb[cc];
        outr[cc] = ov;
        outhr[cc] = __float2half(ov);
    }
}

// ============ misc elementwise ============
__global__ void repmean_kernel(const float* __restrict__ inp, const float* __restrict__ rep_w,
                               float* __restrict__ out)
{
    int b = blockIdx.x, c = threadIdx.x;
    const float* base = inp + (size_t)b*Tc*Cc + c;
    float rw = rep_w[c];
    float s = 0.f;
    for (int t=0;t<Tc;t++) s += fmaxf(rw * base[(size_t)t*Cc], 0.f);
    out[b*Cc + c] = s * (1.f/Tc);
}

__global__ void gate_kernel(const __half* __restrict__ gates, const float* __restrict__ gi,
                            const float* __restrict__ mem_final, const float* __restrict__ mem0,
                            const float* __restrict__ ib, const float* __restrict__ fb,
                            float* __restrict__ nm, __half* __restrict__ nmh)
{
    size_t n = (size_t)Bc*Mc*Cc;
    size_t i = (size_t)blockIdx.x*blockDim.x + threadIdx.x;
    size_t st = (size_t)gridDim.x*blockDim.x;
    float ibv = ib[0], fbv = fb[0];
    for (; i < n; i += st) {
        int c = (int)(i % Cc);
        size_t bm = i / Cc;
        int b = (int)(bm / Mc);
        float gI = __half2float(gates[bm*2*Cc + c])      + gi[b*2*Cc + c]      + ibv;
        float gF = __half2float(gates[bm*2*Cc + Cc + c]) + gi[b*2*Cc + Cc + c] + fbv;
        float igv = 1.f/(1.f + __expf(-gI));
        float fgv = 1.f/(1.f + __expf(-gF));
        float ov = igv * tanhf(mem_final[i]) + fgv * mem0[i];
        nm[i] = ov;
        nmh[i] = __float2half(ov);
    }
}

// ============ launch ============
extern "C" void kernel_launch(void* const* d_in, const int* in_sizes, int n_in,
                              void* d_out, int out_size)
{
    const float* ipts   = (const float*)d_in[0];
    const float* memory = (const float*)d_in[1];
    const float* Wq=(const float*)d_in[2],  *bq=(const float*)d_in[3];
    const float* Wk=(const float*)d_in[4],  *bk=(const float*)d_in[5];
    const float* Wv=(const float*)d_in[6],  *bv=(const float*)d_in[7];
    const float* Wm=(const float*)d_in[8],  *bm=(const float*)d_in[9];
    const float* g1=(const float*)d_in[10], *b1=(const float*)d_in[11];
    const float* g2=(const float*)d_in[12], *b2=(const float*)d_in[13];
    const float* Wp=(const float*)d_in[14], *bp=(const float*)d_in[15];
    const float* rep_w=(const float*)d_in[16];
    const float* Wig=(const float*)d_in[17], *big=(const float*)d_in[18];
    const float* Wmg=(const float*)d_in[19], *bmg=(const float*)d_in[20];
    const float* fb=(const float*)d_in[21], *ib=(const float*)d_in[22];

    float* out_nm = (float*)d_out;
    float* out_hx = out_nm + (size_t)Bc*Mc*Cc;

    float *inp,*mem,*qb,*kvs,*gt,*rm,*gi,*bkv;
    __half *ao_h,*h2_h;
    __half *ipts_h,*inp_h,*mem_h,*h1_h,*tm_h,*nm_h;
    __half *WqT,*WkvT,*WmT,*WpT,*WmgT;
    cudaGetSymbolAddress((void**)&inp, d_inp);
    cudaGetSymbolAddress((void**)&mem, d_mem);
    cudaGetSymbolAddress((void**)&qb,  d_qb);
    cudaGetSymbolAddress((void**)&kvs, d_kvs);
    cudaGetSymbolAddress((void**)&gt,  d_gt);
    cudaGetSymbolAddress((void**)&rm,  d_rm);
    cudaGetSymbolAddress((void**)&gi,  d_gi);
    cudaGetSymbolAddress((void**)&bkv, d_bkv);
    cudaGetSymbolAddress((void**)&ao_h, d_ao_h);
    cudaGetSymbolAddress((void**)&h2_h, d_h2_h);
    cudaGetSymbolAddress((void**)&ipts_h, d_ipts_h);
    cudaGetSymbolAddress((void**)&inp_h,  d_inp_h);
    cudaGetSymbolAddress((void**)&mem_h,  d_mem_h);
    cudaGetSymbolAddress((void**)&h1_h,   d_h1_h);
    cudaGetSymbolAddress((void**)&tm_h,   d_tm_h);
    cudaGetSymbolAddress((void**)&nm_h,   d_nm_h);
    cudaGetSymbolAddress((void**)&WqT, d_WqT);
    cudaGetSymbolAddress((void**)&WkvT, d_WkvT);
    cudaGetSymbolAddress((void**)&WmT, d_WmT);
    cudaGetSymbolAddress((void**)&WpT, d_WpT);
    cudaGetSymbolAddress((void**)&WmgT, d_WmgT);

    cudaFuncSetAttribute(attn_topk_kernel, cudaFuncAttributeMaxDynamicSharedMemorySize, SMEM_TOPK);
    cudaFuncSetAttribute(attn_hx_kernel,   cudaFuncAttributeMaxDynamicSharedMemorySize, SMEM_HX);
    cudaFuncSetAttribute(f16_gemm_kernel,  cudaFuncAttributeMaxDynamicSharedMemorySize, TG_SMEM);

    TPack tp;
    tp.in[0]=Wq;  tp.out[0]=WqT;           tp.C[0]=Cc;
    tp.in[1]=Wk;  tp.out[1]=WkvT;          tp.C[1]=Cc;
    tp.in[2]=Wv;  tp.out[2]=WkvT + Cc*Cc;  tp.C[2]=Cc;
    tp.in[3]=Wm;  tp.out[3]=WmT;           tp.C[3]=Cc;
    tp.in[4]=Wp;  tp.out[4]=WpT;           tp.C[4]=Cc;
    tp.in[5]=Wmg; tp.out[5]=WmgT;          tp.C[5]=2*Cc;
    tp.bk = bk; tp.bv = bv; tp.bkv = bkv;
    transpose_all_kernel<<<dim3(32,16,6), 256>>>(tp);
    convert_pre_kernel<<<2048, 256>>>(ipts, memory, ipts_h, mem_h, tm_h);

    auto tgemm = [&](const __half* A, const __half* WT, const float* bias,
                     float* of, __half* oh, int N, int NO, int relu){
        f16_gemm_kernel<<<dim3(NO/128, (N+127)/128), 256, TG_SMEM>>>(
            A, WT, bias, of, oh, N, Cc, NO, relu);
    };

    // inp = ipts @ Wp + bp (float + half); fused k|v from inp_h
    tgemm(ipts_h, WpT, bp, inp, inp_h, Bc*Tc, Cc, 0);
    tgemm(inp_h, WkvT, bkv, kvs, nullptr, Bc*Tc, KVS, 0);

    for (int blk = 0; blk < NBLK; blk++) {
        tgemm(mem_h, WqT, bq, qb, nullptr, Bc*Mc, Cc, 0);
        attn_topk_kernel<<<dim3(Bc*Hc, Q_BLOCKS), 256, SMEM_TOPK>>>(qb, kvs, ao_h);
        const float* xres = (blk == 0) ? memory : mem;
        add_ln_kernel<<<(Bc*Mc + 7)/8, 256>>>(xres, ao_h, g1, b1, mem, mem_h, Bc*Mc);
        tgemm(mem_h, WmT, bm, nullptr, h1_h, Bc*Mc, Cc, 1);
        tgemm(h1_h,  WmT, bm, nullptr, h2_h, Bc*Mc, Cc, 1);
        add_ln_kernel<<<(Bc*Mc + 7)/8, 256>>>(mem, h2_h, g2, b2, mem, mem_h, Bc*Mc);
    }

    // gates (logits as half, stored in gt buffer)
    repmean_kernel<<<Bc, Cc>>>(inp, rep_w, rm);
    gemm_kernel<<<dim3(2*Cc/64, 1), 256>>>(rm, Wig, big, gi, Bc, Cc, 2*Cc, 0);
    __half* gth = (__half*)gt;
    f16_gemm_kernel<<<dim3((2*Cc)/128, (Bc*Mc+127)/128), 256, TG_SMEM>>>(
        tm_h, WmgT, bmg, nullptr, gth, Bc*Mc, Cc, 2*Cc, 0);
    gate_kernel<<<2048, 256>>>(gth, gi, mem, memory, ib, fb, out_nm, nm_h);

    // hx (gt buffer reused as float kv_big AFTER gate consumed the half logits)
    tgemm(inp_h, WqT, bq, qb, nullptr, Bc*Tc, Cc, 0);
    tgemm(nm_h, WkvT, bkv, gt, nullptr, Bc*Mc, KVS, 0);
    attn_hx_kernel<<<dim3(Bc*Hc, Tc/32), 256, SMEM_HX>>>(qb, gt, out_hx);
}